// round 1
// baseline (speedup 1.0000x reference)
#include <cuda_runtime.h>
#include <math.h>

#define T_TOK 2048
#define H_DIM 1024
#define E_NUM 8
#define I_DIM 2816
#define NSEL 2

// ---------------- device scratch (no allocations allowed) ----------------
__device__ int   g_count[E_NUM];                       // tokens per expert
__device__ int   g_tok[E_NUM * T_TOK];                 // assignment slot ids (2t+k)
__device__ float g_wgt[NSEL * T_TOK];                  // softmax weight per slot
__device__ float g_A[(size_t)NSEL * T_TOK * I_DIM];    // SwiGLU activations, slot-indexed (46 MB)

// ---------------- zero the per-expert counters ----------------
__global__ void k_zero() {
    if (threadIdx.x < E_NUM) g_count[threadIdx.x] = 0;
}

// ---------------- router: logits, top-2, softmax, build expert lists ------
__global__ void k_router(const float* __restrict__ x, const float* __restrict__ wr) {
    int t = blockIdx.x * 8 + (threadIdx.x >> 5);
    int lane = threadIdx.x & 31;
    if (t >= T_TOK) return;

    float acc[E_NUM];
#pragma unroll
    for (int e = 0; e < E_NUM; e++) acc[e] = 0.f;

    const float* xr = x + (size_t)t * H_DIM;
    for (int h = lane; h < H_DIM; h += 32) {
        float xv = xr[h];
        const float* wrow = wr + (size_t)h * E_NUM;
#pragma unroll
        for (int e = 0; e < E_NUM; e++) acc[e] += xv * wrow[e];
    }
#pragma unroll
    for (int off = 16; off > 0; off >>= 1) {
#pragma unroll
        for (int e = 0; e < E_NUM; e++)
            acc[e] += __shfl_down_sync(0xFFFFFFFFu, acc[e], off);
    }

    if (lane == 0) {
        // top-1 (ties -> lowest index, matching jax top_k)
        int i0 = 0; float v0 = acc[0];
#pragma unroll
        for (int e = 1; e < E_NUM; e++) if (acc[e] > v0) { v0 = acc[e]; i0 = e; }
        // top-2
        int i1 = -1; float v1 = -INFINITY;
#pragma unroll
        for (int e = 0; e < E_NUM; e++) {
            if (e == i0) continue;
            if (acc[e] > v1) { v1 = acc[e]; i1 = e; }
        }
        // softmax over [v0, v1]
        float w0 = 1.f / (1.f + expf(v1 - v0));
        float w1 = 1.f - w0;

        int p0 = atomicAdd(&g_count[i0], 1);
        g_tok[i0 * T_TOK + p0] = 2 * t;
        int p1 = atomicAdd(&g_count[i1], 1);
        g_tok[i1 * T_TOK + p1] = 2 * t + 1;
        g_wgt[2 * t]     = w0;
        g_wgt[2 * t + 1] = w1;
    }
}

// ---------------- grouped GEMM: gate + up fused, SiLU epilogue ------------
// C tile 64x64, K tile 16, 256 threads, each thread 4x4 outputs for BOTH mats.
__global__ void __launch_bounds__(256) k_gateup(const float* __restrict__ x,
                                                const float* __restrict__ wg,
                                                const float* __restrict__ wu) {
    const int e = blockIdx.z;
    const int cnt = g_count[e];
    const int m0 = blockIdx.y * 64;
    if (m0 >= cnt) return;
    const int n0 = blockIdx.x * 64;

    __shared__ float Xs[64][17];
    __shared__ float Gs[16][64];
    __shared__ float Us[16][64];
    __shared__ int   slots[64];

    const int tid = threadIdx.x;
    if (tid < 64) {
        int m = m0 + tid;
        slots[tid] = (m < cnt) ? g_tok[e * T_TOK + m] : -1;
    }
    __syncthreads();

    const int ty = tid >> 4, tx = tid & 15;
    float ag[4][4] = {}, au[4][4] = {};

    const float* wge = wg + (size_t)e * H_DIM * I_DIM;
    const float* wue = wu + (size_t)e * H_DIM * I_DIM;

    for (int k0 = 0; k0 < H_DIM; k0 += 16) {
        // load X tile (gathered rows), zero-fill invalid rows
#pragma unroll
        for (int l = tid; l < 64 * 16; l += 256) {
            int m = l >> 4, k = l & 15;
            int s = slots[m];
            Xs[m][k] = (s >= 0) ? x[(size_t)(s >> 1) * H_DIM + k0 + k] : 0.f;
        }
        // load W tiles
#pragma unroll
        for (int l = tid; l < 16 * 64; l += 256) {
            int k = l >> 6, n = l & 63;
            size_t off = (size_t)(k0 + k) * I_DIM + n0 + n;
            Gs[k][n] = wge[off];
            Us[k][n] = wue[off];
        }
        __syncthreads();

#pragma unroll
        for (int kk = 0; kk < 16; kk++) {
            float av[4], gv[4], uv[4];
#pragma unroll
            for (int i = 0; i < 4; i++) av[i] = Xs[ty * 4 + i][kk];
#pragma unroll
            for (int j = 0; j < 4; j++) { gv[j] = Gs[kk][tx * 4 + j]; uv[j] = Us[kk][tx * 4 + j]; }
#pragma unroll
            for (int i = 0; i < 4; i++)
#pragma unroll
                for (int j = 0; j < 4; j++) {
                    ag[i][j] = fmaf(av[i], gv[j], ag[i][j]);
                    au[i][j] = fmaf(av[i], uv[j], au[i][j]);
                }
        }
        __syncthreads();
    }

    // epilogue: a = silu(g) * u  ->  g_A[slot][n]
#pragma unroll
    for (int i = 0; i < 4; i++) {
        int mi = ty * 4 + i;
        int s = slots[mi];
        if (s < 0) continue;
        float* arow = g_A + (size_t)s * I_DIM + n0 + tx * 4;
#pragma unroll
        for (int j = 0; j < 4; j++) {
            float g = ag[i][j];
            float a = (g / (1.f + expf(-g))) * au[i][j];
            arow[j] = a;
        }
    }
}

// ---------------- grouped GEMM: down proj + bias + weighted combine -------
__global__ void __launch_bounds__(256) k_down(const float* __restrict__ wd,
                                              const float* __restrict__ bd,
                                              float* __restrict__ out) {
    const int e = blockIdx.z;
    const int cnt = g_count[e];
    const int m0 = blockIdx.y * 64;
    if (m0 >= cnt) return;
    const int n0 = blockIdx.x * 64;

    __shared__ float As[64][17];
    __shared__ float Bs[16][64];
    __shared__ int   slots[64];

    const int tid = threadIdx.x;
    if (tid < 64) {
        int m = m0 + tid;
        slots[tid] = (m < cnt) ? g_tok[e * T_TOK + m] : -1;
    }
    __syncthreads();

    const int ty = tid >> 4, tx = tid & 15;
    float acc[4][4] = {};

    const float* wde = wd + (size_t)e * I_DIM * H_DIM;

    for (int k0 = 0; k0 < I_DIM; k0 += 16) {
#pragma unroll
        for (int l = tid; l < 64 * 16; l += 256) {
            int m = l >> 4, k = l & 15;
            int s = slots[m];
            As[m][k] = (s >= 0) ? g_A[(size_t)s * I_DIM + k0 + k] : 0.f;
        }
#pragma unroll
        for (int l = tid; l < 16 * 64; l += 256) {
            int k = l >> 6, n = l & 63;
            Bs[k][n] = wde[(size_t)(k0 + k) * H_DIM + n0 + n];
        }
        __syncthreads();

#pragma unroll
        for (int kk = 0; kk < 16; kk++) {
            float av[4], bv[4];
#pragma unroll
            for (int i = 0; i < 4; i++) av[i] = As[ty * 4 + i][kk];
#pragma unroll
            for (int j = 0; j < 4; j++) bv[j] = Bs[kk][tx * 4 + j];
#pragma unroll
            for (int i = 0; i < 4; i++)
#pragma unroll
                for (int j = 0; j < 4; j++)
                    acc[i][j] = fmaf(av[i], bv[j], acc[i][j]);
        }
        __syncthreads();
    }

    // epilogue: out[t] += w * (acc + b_down[e])
#pragma unroll
    for (int i = 0; i < 4; i++) {
        int mi = ty * 4 + i;
        int s = slots[mi];
        if (s < 0) continue;
        float w = g_wgt[s];
        int t = s >> 1;
        float* orow = out + (size_t)t * H_DIM + n0 + tx * 4;
        const float* brow = bd + (size_t)e * H_DIM + n0 + tx * 4;
#pragma unroll
        for (int j = 0; j < 4; j++) {
            float v = (acc[i][j] + brow[j]) * w;
            atomicAdd(&orow[j], v);   // exactly 2 commutative adds per element -> deterministic
        }
    }
}

// ---------------- launch ----------------
extern "C" void kernel_launch(void* const* d_in, const int* in_sizes, int n_in,
                              void* d_out, int out_size) {
    const float* x  = (const float*)d_in[0];
    const float* wr = (const float*)d_in[1];
    const float* wg = (const float*)d_in[2];
    const float* wu = (const float*)d_in[3];
    const float* wd = (const float*)d_in[4];
    const float* bd = (const float*)d_in[5];
    float* out = (float*)d_out;

    cudaMemsetAsync(out, 0, (size_t)out_size * sizeof(float));
    k_zero<<<1, 32>>>();
    k_router<<<T_TOK / 8, 256>>>(x, wr);
    k_gateup<<<dim3(I_DIM / 64, T_TOK / 64, E_NUM), 256>>>(x, wg, wu);
    k_down<<<dim3(H_DIM / 64, T_TOK / 64, E_NUM), 256>>>(wd, bd, out);
}

// round 3
// speedup vs baseline: 2.7228x; 2.7228x over previous
#include <cuda_runtime.h>
#include <cuda_bf16.h>
#include <math.h>
#include <stdint.h>

#define T_TOK 2048
#define H_DIM 1024
#define E_NUM 8
#define I_DIM 2816
#define NSLOT (2*T_TOK)

// ---------------- device scratch ----------------
__device__ int   g_count[E_NUM];
__device__ int   g_base[E_NUM];
__device__ int   g_tok[E_NUM*T_TOK];
__device__ float g_wgt[NSLOT];
__device__ int   g_rowtok[NSLOT];
__device__ __nv_bfloat16 g_Xhi[(size_t)NSLOT*H_DIM];
__device__ __nv_bfloat16 g_Xlo[(size_t)NSLOT*H_DIM];
__device__ __nv_bfloat16 g_Wg_hi[(size_t)E_NUM*I_DIM*H_DIM];
__device__ __nv_bfloat16 g_Wg_lo[(size_t)E_NUM*I_DIM*H_DIM];
__device__ __nv_bfloat16 g_Wu_hi[(size_t)E_NUM*I_DIM*H_DIM];
__device__ __nv_bfloat16 g_Wu_lo[(size_t)E_NUM*I_DIM*H_DIM];
__device__ __nv_bfloat16 g_Wd_hi[(size_t)E_NUM*H_DIM*I_DIM];
__device__ __nv_bfloat16 g_Wd_lo[(size_t)E_NUM*H_DIM*I_DIM];
__device__ __nv_bfloat16 g_Ahi[(size_t)NSLOT*I_DIM];
__device__ __nv_bfloat16 g_Alo[(size_t)NSLOT*I_DIM];

// ---------------- helpers ----------------
__device__ __forceinline__ uint32_t s2u(const void* p){
    uint32_t a;
    asm("{ .reg .u64 t; cvta.to.shared.u64 t, %1; cvt.u32.u64 %0, t; }" : "=r"(a) : "l"(p));
    return a;
}
__device__ __forceinline__ void cpa(uint32_t dst, const void* src){
    asm volatile("cp.async.cg.shared.global [%0], [%1], 16;" :: "r"(dst), "l"(src));
}
__device__ __forceinline__ void cpcommit(){ asm volatile("cp.async.commit_group;" ::: "memory"); }
template<int N> __device__ __forceinline__ void cpwait(){ asm volatile("cp.async.wait_group %0;" :: "n"(N) : "memory"); }

__device__ __forceinline__ void mma_bf16(float* d, const uint32_t* a, const uint32_t* b){
    asm volatile(
        "mma.sync.aligned.m16n8k16.row.col.f32.bf16.bf16.f32 "
        "{%0,%1,%2,%3}, {%4,%5,%6,%7}, {%8,%9}, {%0,%1,%2,%3};"
        : "+f"(d[0]), "+f"(d[1]), "+f"(d[2]), "+f"(d[3])
        : "r"(a[0]), "r"(a[1]), "r"(a[2]), "r"(a[3]), "r"(b[0]), "r"(b[1]));
}
__device__ __forceinline__ unsigned short bu(__nv_bfloat16 b){
    return *reinterpret_cast<unsigned short*>(&b);
}

// ---------------- small kernels ----------------
__global__ void k_zero(){ if (threadIdx.x < E_NUM) g_count[threadIdx.x] = 0; }

__global__ void k_router(const float* __restrict__ x, const float* __restrict__ wr){
    int t = blockIdx.x*8 + (threadIdx.x>>5);
    int lane = threadIdx.x & 31;
    if (t >= T_TOK) return;
    float acc[E_NUM];
#pragma unroll
    for (int e=0;e<E_NUM;e++) acc[e]=0.f;
    const float* xr = x + (size_t)t*H_DIM;
    for (int h=lane; h<H_DIM; h+=32){
        float xv = xr[h];
        const float* wrow = wr + (size_t)h*E_NUM;
#pragma unroll
        for (int e=0;e<E_NUM;e++) acc[e] += xv*wrow[e];
    }
#pragma unroll
    for (int off=16; off>0; off>>=1)
#pragma unroll
        for (int e=0;e<E_NUM;e++) acc[e] += __shfl_down_sync(0xFFFFFFFFu, acc[e], off);
    if (lane==0){
        int i0=0; float v0=acc[0];
#pragma unroll
        for (int e=1;e<E_NUM;e++) if (acc[e]>v0){ v0=acc[e]; i0=e; }
        int i1=-1; float v1=-INFINITY;
#pragma unroll
        for (int e=0;e<E_NUM;e++){ if (e==i0) continue; if (acc[e]>v1){ v1=acc[e]; i1=e; } }
        float w0 = 1.f/(1.f+expf(v1-v0));
        float w1 = 1.f - w0;
        int p0 = atomicAdd(&g_count[i0],1); g_tok[i0*T_TOK+p0] = 2*t;
        int p1 = atomicAdd(&g_count[i1],1); g_tok[i1*T_TOK+p1] = 2*t+1;
        g_wgt[2*t]=w0; g_wgt[2*t+1]=w1;
    }
}

__global__ void k_prefix(){
    if (threadIdx.x==0){
        int s=0;
#pragma unroll
        for (int e=0;e<E_NUM;e++){ g_base[e]=s; s+=g_count[e]; }
    }
}

__global__ void __launch_bounds__(256) k_prep(const float* __restrict__ x){
    int e = blockIdx.y, p = blockIdx.x;
    if (p >= g_count[e]) return;
    int r = g_base[e] + p;
    int slot = g_tok[e*T_TOK + p];
    if (threadIdx.x==0) g_rowtok[r] = slot;
    int t = slot >> 1;
    float4 v = ((const float4*)(x + (size_t)t*H_DIM))[threadIdx.x];
    float xs[4] = {v.x, v.y, v.z, v.w};
    unsigned short h[4], l[4];
#pragma unroll
    for (int i=0;i<4;i++){
        __nv_bfloat16 hb = __float2bfloat16_rn(xs[i]);
        h[i] = bu(hb);
        l[i] = bu(__float2bfloat16_rn(xs[i] - __bfloat162float(hb)));
    }
    uint2 hh, ll;
    hh.x = (uint32_t)h[0] | ((uint32_t)h[1]<<16); hh.y = (uint32_t)h[2] | ((uint32_t)h[3]<<16);
    ll.x = (uint32_t)l[0] | ((uint32_t)l[1]<<16); ll.y = (uint32_t)l[2] | ((uint32_t)l[3]<<16);
    *(uint2*)(g_Xhi + (size_t)r*H_DIM + threadIdx.x*4) = hh;
    *(uint2*)(g_Xlo + (size_t)r*H_DIM + threadIdx.x*4) = ll;
}

// transpose-convert: W[e][K][N] fp32 -> Oh/Ol[e][N][K] bf16 hi/lo
__global__ void __launch_bounds__(256) k_convert(const float* __restrict__ W,
                                                 __nv_bfloat16* __restrict__ Oh,
                                                 __nv_bfloat16* __restrict__ Ol,
                                                 int K, int N){
    __shared__ float ts[32][33];
    int e = blockIdx.z;
    int n0 = blockIdx.x*32, k0 = blockIdx.y*32;
    const float* We = W + (size_t)e*K*N;
    int tid = threadIdx.x;
    int r = tid>>3, c4 = (tid&7)*4;
    float4 v = *(const float4*)(We + (size_t)(k0+r)*N + n0 + c4);
    ts[r][c4+0]=v.x; ts[r][c4+1]=v.y; ts[r][c4+2]=v.z; ts[r][c4+3]=v.w;
    __syncthreads();
    unsigned short h[4], l[4];
#pragma unroll
    for (int i=0;i<4;i++){
        float xv = ts[c4+i][r];
        __nv_bfloat16 hb = __float2bfloat16_rn(xv);
        h[i] = bu(hb);
        l[i] = bu(__float2bfloat16_rn(xv - __bfloat162float(hb)));
    }
    size_t ob = ((size_t)e*N + n0 + r)*K + k0 + c4;
    uint2 hh, ll;
    hh.x = (uint32_t)h[0] | ((uint32_t)h[1]<<16); hh.y = (uint32_t)h[2] | ((uint32_t)h[3]<<16);
    ll.x = (uint32_t)l[0] | ((uint32_t)l[1]<<16); ll.y = (uint32_t)l[2] | ((uint32_t)l[3]<<16);
    *(uint2*)(Oh + ob) = hh;
    *(uint2*)(Ol + ob) = ll;
}

// ======================== GEMM 1: gate+up, SiLU epilogue ========================
// CTA 128(M) x 64(N), K chunks of 32, 8 warps (4 M x 2 N), warp tile 32x32.
// SMEM stage: Ah[128][80B] Al Gh[64][80B] Gl Uh Ul  = 40960 B, double buffered.
#define ST_GU 40960
__global__ void __launch_bounds__(256,1) k_gemm_gateup(){
    const int e = blockIdx.z;
    const int cnt = g_count[e];
    const int m0 = blockIdx.y*128;
    if (m0 >= cnt) return;
    const int n0 = blockIdx.x*64;
    const int rowbase = g_base[e] + m0;
    const int vr = min(128, cnt - m0);

    extern __shared__ char sm[];
    uint32_t sb = s2u(sm);

    const int tid = threadIdx.x;
    const int lane = tid & 31, wid = tid >> 5;
    const int wm = wid & 3, wn = wid >> 2;
    const int r0 = lane >> 2, cq = (lane & 3)*4;

    const char* xh = (const char*)g_Xhi + (size_t)rowbase*H_DIM*2;
    const char* xl = (const char*)g_Xlo + (size_t)rowbase*H_DIM*2;
    size_t wo = ((size_t)e*I_DIM + n0)*H_DIM*2;
    const char* gh = (const char*)g_Wg_hi + wo;
    const char* gl = (const char*)g_Wg_lo + wo;
    const char* uh = (const char*)g_Wu_hi + wo;
    const char* ul = (const char*)g_Wu_lo + wo;

    float accG[2][4][4] = {};
    float accU[2][4][4] = {};

    auto load_stage = [&](int kc){
        uint32_t stg = sb + (kc & 1)*ST_GU;
        int kb = kc*64;  // bytes along K
#pragma unroll
        for (int c=0;c<4;c++){   // A: 1024 chunks (hi,lo)
            int idx = tid + 256*c;
            int mat = idx >> 9, rem = idx & 511, row = rem >> 2, seg = rem & 3;
            int srow = min(rowbase + row, NSLOT-1) - rowbase;
            const char* s = (mat ? xl : xh) + (size_t)srow*2048 + kb + seg*16;
            cpa(stg + mat*10240 + row*80 + seg*16, s);
        }
#pragma unroll
        for (int c=0;c<4;c++){   // B: 1024 chunks (Gh,Gl,Uh,Ul)
            int idx = tid + 256*c;
            int mat = idx >> 8, rem = idx & 255, row = rem >> 2, seg = rem & 3;
            const char* base = (mat==0) ? gh : (mat==1) ? gl : (mat==2) ? uh : ul;
            const char* s = base + (size_t)row*2048 + kb + seg*16;
            cpa(stg + 20480 + mat*5120 + row*80 + seg*16, s);
        }
        cpcommit();
    };

    auto compute = [&](int kc){
        const char* st = sm + (kc & 1)*ST_GU;
#pragma unroll
        for (int k16=0;k16<2;k16++){
            int ko = k16*32;
            uint32_t ah[2][4], al[2][4];
#pragma unroll
            for (int mi=0;mi<2;mi++){
                const char* pa = st + (wm*32 + mi*16 + r0)*80 + ko + cq;
                ah[mi][0]=*(const uint32_t*)(pa);
                ah[mi][1]=*(const uint32_t*)(pa+640);
                ah[mi][2]=*(const uint32_t*)(pa+16);
                ah[mi][3]=*(const uint32_t*)(pa+656);
                const char* pl = pa + 10240;
                al[mi][0]=*(const uint32_t*)(pl);
                al[mi][1]=*(const uint32_t*)(pl+640);
                al[mi][2]=*(const uint32_t*)(pl+16);
                al[mi][3]=*(const uint32_t*)(pl+656);
            }
            uint32_t bgh[4][2], bgl[4][2], buh[4][2], bul[4][2];
#pragma unroll
            for (int ni=0;ni<4;ni++){
                const char* pb = st + 20480 + (wn*32 + ni*8 + r0)*80 + ko + cq;
                bgh[ni][0]=*(const uint32_t*)(pb);        bgh[ni][1]=*(const uint32_t*)(pb+16);
                bgl[ni][0]=*(const uint32_t*)(pb+5120);   bgl[ni][1]=*(const uint32_t*)(pb+5136);
                buh[ni][0]=*(const uint32_t*)(pb+10240);  buh[ni][1]=*(const uint32_t*)(pb+10256);
                bul[ni][0]=*(const uint32_t*)(pb+15360);  bul[ni][1]=*(const uint32_t*)(pb+15376);
            }
#pragma unroll
            for (int mi=0;mi<2;mi++)
#pragma unroll
                for (int ni=0;ni<4;ni++){
                    mma_bf16(accG[mi][ni], ah[mi], bgh[ni]);
                    mma_bf16(accG[mi][ni], ah[mi], bgl[ni]);
                    mma_bf16(accG[mi][ni], al[mi], bgh[ni]);
                    mma_bf16(accU[mi][ni], ah[mi], buh[ni]);
                    mma_bf16(accU[mi][ni], ah[mi], bul[ni]);
                    mma_bf16(accU[mi][ni], al[mi], buh[ni]);
                }
        }
    };

    load_stage(0);
    const int NK = H_DIM/32;  // 32
    for (int kc=0; kc<NK; kc++){
        if (kc+1 < NK){ load_stage(kc+1); cpwait<1>(); }
        else cpwait<0>();
        __syncthreads();
        compute(kc);
        __syncthreads();
    }

    // epilogue: a = silu(g)*u -> g_Ahi/g_Alo (hi/lo split)
#pragma unroll
    for (int mi=0;mi<2;mi++)
#pragma unroll
        for (int hf=0;hf<2;hf++){
            int row = wm*32 + mi*16 + r0 + hf*8;
            if (row < vr){
                size_t rb = (size_t)(rowbase + row)*I_DIM;
#pragma unroll
                for (int ni=0;ni<4;ni++){
                    int n = n0 + wn*32 + ni*8 + (lane&3)*2;
                    float g0 = accG[mi][ni][hf*2+0], g1 = accG[mi][ni][hf*2+1];
                    float u0 = accU[mi][ni][hf*2+0], u1 = accU[mi][ni][hf*2+1];
                    float a0 = g0/(1.f+expf(-g0))*u0;
                    float a1 = g1/(1.f+expf(-g1))*u1;
                    __nv_bfloat16 h0=__float2bfloat16_rn(a0), h1=__float2bfloat16_rn(a1);
                    __nv_bfloat16 l0=__float2bfloat16_rn(a0-__bfloat162float(h0));
                    __nv_bfloat16 l1=__float2bfloat16_rn(a1-__bfloat162float(h1));
                    *(uint32_t*)((char*)g_Ahi + (rb+n)*2) = (uint32_t)bu(h0) | ((uint32_t)bu(h1)<<16);
                    *(uint32_t*)((char*)g_Alo + (rb+n)*2) = (uint32_t)bu(l0) | ((uint32_t)bu(l1)<<16);
                }
            }
        }
}

// ======================== GEMM 2: down + bias + weighted combine ========================
// SMEM stage: Ah[128][80B] Al Wh[64][80B] Wl = 30720 B, double buffered.
#define ST_DN 30720
__global__ void __launch_bounds__(256,1) k_gemm_down(const float* __restrict__ bd,
                                                     float* __restrict__ out){
    const int e = blockIdx.z;
    const int cnt = g_count[e];
    const int m0 = blockIdx.y*128;
    if (m0 >= cnt) return;
    const int n0 = blockIdx.x*64;
    const int rowbase = g_base[e] + m0;
    const int vr = min(128, cnt - m0);

    extern __shared__ char sm[];
    uint32_t sb = s2u(sm);

    const int tid = threadIdx.x;
    const int lane = tid & 31, wid = tid >> 5;
    const int wm = wid & 3, wn = wid >> 2;
    const int r0 = lane >> 2, cq = (lane & 3)*4;

    const char* ah = (const char*)g_Ahi + (size_t)rowbase*I_DIM*2;
    const char* al = (const char*)g_Alo + (size_t)rowbase*I_DIM*2;
    size_t wo = ((size_t)e*H_DIM + n0)*I_DIM*2;
    const char* wh = (const char*)g_Wd_hi + wo;
    const char* wl = (const char*)g_Wd_lo + wo;
    const size_t strA = (size_t)I_DIM*2;  // 5632

    float acc[2][4][4] = {};

    auto load_stage = [&](int kc){
        uint32_t stg = sb + (kc & 1)*ST_DN;
        int kb = kc*64;
#pragma unroll
        for (int c=0;c<4;c++){   // A: 1024 chunks
            int idx = tid + 256*c;
            int mat = idx >> 9, rem = idx & 511, row = rem >> 2, seg = rem & 3;
            int srow = min(rowbase + row, NSLOT-1) - rowbase;
            const char* s = (mat ? al : ah) + (size_t)srow*strA + kb + seg*16;
            cpa(stg + mat*10240 + row*80 + seg*16, s);
        }
#pragma unroll
        for (int c=0;c<2;c++){   // B: 512 chunks (Wh,Wl)
            int idx = tid + 256*c;
            int mat = idx >> 8, rem = idx & 255, row = rem >> 2, seg = rem & 3;
            const char* s = (mat ? wl : wh) + (size_t)row*strA + kb + seg*16;
            cpa(stg + 20480 + mat*5120 + row*80 + seg*16, s);
        }
        cpcommit();
    };

    auto compute = [&](int kc){
        const char* st = sm + (kc & 1)*ST_DN;
#pragma unroll
        for (int k16=0;k16<2;k16++){
            int ko = k16*32;
            uint32_t a_h[2][4], a_l[2][4];
#pragma unroll
            for (int mi=0;mi<2;mi++){
                const char* pa = st + (wm*32 + mi*16 + r0)*80 + ko + cq;
                a_h[mi][0]=*(const uint32_t*)(pa);
                a_h[mi][1]=*(const uint32_t*)(pa+640);
                a_h[mi][2]=*(const uint32_t*)(pa+16);
                a_h[mi][3]=*(const uint32_t*)(pa+656);
                const char* pl = pa + 10240;
                a_l[mi][0]=*(const uint32_t*)(pl);
                a_l[mi][1]=*(const uint32_t*)(pl+640);
                a_l[mi][2]=*(const uint32_t*)(pl+16);
                a_l[mi][3]=*(const uint32_t*)(pl+656);
            }
            uint32_t bwh[4][2], bwl[4][2];
#pragma unroll
            for (int ni=0;ni<4;ni++){
                const char* pb = st + 20480 + (wn*32 + ni*8 + r0)*80 + ko + cq;
                bwh[ni][0]=*(const uint32_t*)(pb);       bwh[ni][1]=*(const uint32_t*)(pb+16);
                bwl[ni][0]=*(const uint32_t*)(pb+5120);  bwl[ni][1]=*(const uint32_t*)(pb+5136);
            }
#pragma unroll
            for (int mi=0;mi<2;mi++)
#pragma unroll
                for (int ni=0;ni<4;ni++){
                    mma_bf16(acc[mi][ni], a_h[mi], bwh[ni]);
                    mma_bf16(acc[mi][ni], a_h[mi], bwl[ni]);
                    mma_bf16(acc[mi][ni], a_l[mi], bwh[ni]);
                }
        }
    };

    load_stage(0);
    const int NK = I_DIM/32;  // 88
    for (int kc=0; kc<NK; kc++){
        if (kc+1 < NK){ load_stage(kc+1); cpwait<1>(); }
        else cpwait<0>();
        __syncthreads();
        compute(kc);
        __syncthreads();
    }

    // epilogue: out[t] += w * (acc + b_down[e])   (2 commutative adds -> deterministic)
#pragma unroll
    for (int mi=0;mi<2;mi++)
#pragma unroll
        for (int hf=0;hf<2;hf++){
            int row = wm*32 + mi*16 + r0 + hf*8;
            if (row < vr){
                int slot = g_rowtok[rowbase + row];
                float w = g_wgt[slot];
                int t = slot >> 1;
                float* orow = out + (size_t)t*H_DIM;
                const float* brow = bd + (size_t)e*H_DIM;
#pragma unroll
                for (int ni=0;ni<4;ni++){
                    int n = n0 + wn*32 + ni*8 + (lane&3)*2;
                    float v0 = (acc[mi][ni][hf*2+0] + brow[n])   * w;
                    float v1 = (acc[mi][ni][hf*2+1] + brow[n+1]) * w;
                    atomicAdd(&orow[n],   v0);
                    atomicAdd(&orow[n+1], v1);
                }
            }
        }
}

// ---------------- launch ----------------
extern "C" void kernel_launch(void* const* d_in, const int* in_sizes, int n_in,
                              void* d_out, int out_size){
    const float* x  = (const float*)d_in[0];
    const float* wr = (const float*)d_in[1];
    const float* wg = (const float*)d_in[2];
    const float* wu = (const float*)d_in[3];
    const float* wd = (const float*)d_in[4];
    const float* bd = (const float*)d_in[5];
    float* out = (float*)d_out;

    __nv_bfloat16 *wg_hi, *wg_lo, *wu_hi, *wu_lo, *wd_hi, *wd_lo;
    cudaGetSymbolAddress((void**)&wg_hi, g_Wg_hi);
    cudaGetSymbolAddress((void**)&wg_lo, g_Wg_lo);
    cudaGetSymbolAddress((void**)&wu_hi, g_Wu_hi);
    cudaGetSymbolAddress((void**)&wu_lo, g_Wu_lo);
    cudaGetSymbolAddress((void**)&wd_hi, g_Wd_hi);
    cudaGetSymbolAddress((void**)&wd_lo, g_Wd_lo);

    cudaFuncSetAttribute(k_gemm_gateup, cudaFuncAttributeMaxDynamicSharedMemorySize, 2*ST_GU);
    cudaFuncSetAttribute(k_gemm_down,   cudaFuncAttributeMaxDynamicSharedMemorySize, 2*ST_DN);

    cudaMemsetAsync(out, 0, (size_t)out_size * sizeof(float));
    k_zero<<<1,32>>>();
    k_router<<<T_TOK/8, 256>>>(x, wr);
    k_prefix<<<1,32>>>();
    k_prep<<<dim3(T_TOK, E_NUM), 256>>>(x);

    k_convert<<<dim3(I_DIM/32, H_DIM/32, E_NUM), 256>>>(wg, wg_hi, wg_lo, H_DIM, I_DIM);
    k_convert<<<dim3(I_DIM/32, H_DIM/32, E_NUM), 256>>>(wu, wu_hi, wu_lo, H_DIM, I_DIM);
    k_convert<<<dim3(H_DIM/32, I_DIM/32, E_NUM), 256>>>(wd, wd_hi, wd_lo, I_DIM, H_DIM);

    k_gemm_gateup<<<dim3(I_DIM/64, T_TOK/128, E_NUM), 256, 2*ST_GU>>>();
    k_gemm_down  <<<dim3(H_DIM/64, T_TOK/128, E_NUM), 256, 2*ST_DN>>>(bd, out);
}

// round 4
// speedup vs baseline: 3.2898x; 1.2083x over previous
#include <cuda_runtime.h>
#include <cuda_bf16.h>
#include <math.h>
#include <stdint.h>

#define T_TOK 2048
#define H_DIM 1024
#define E_NUM 8
#define I_DIM 2816
#define NSLOT (2*T_TOK)

// ---------------- device scratch ----------------
__device__ int   g_count[E_NUM];
__device__ int   g_base[E_NUM];
__device__ int   g_tok[E_NUM*T_TOK];
__device__ float g_wgt[NSLOT];
__device__ int   g_rowtok[NSLOT];
__device__ __nv_bfloat16 g_Xhi[(size_t)NSLOT*H_DIM];
__device__ __nv_bfloat16 g_Xlo[(size_t)NSLOT*H_DIM];
__device__ __nv_bfloat16 g_Wg_hi[(size_t)E_NUM*I_DIM*H_DIM];
__device__ __nv_bfloat16 g_Wg_lo[(size_t)E_NUM*I_DIM*H_DIM];
__device__ __nv_bfloat16 g_Wu_hi[(size_t)E_NUM*I_DIM*H_DIM];
__device__ __nv_bfloat16 g_Wu_lo[(size_t)E_NUM*I_DIM*H_DIM];
__device__ __nv_bfloat16 g_Wd_hi[(size_t)E_NUM*H_DIM*I_DIM];
__device__ __nv_bfloat16 g_Wd_lo[(size_t)E_NUM*H_DIM*I_DIM];
__device__ __nv_bfloat16 g_Ahi[(size_t)NSLOT*I_DIM];
__device__ __nv_bfloat16 g_Alo[(size_t)NSLOT*I_DIM];

// ---------------- helpers ----------------
__device__ __forceinline__ uint32_t s2u(const void* p){
    uint32_t a;
    asm("{ .reg .u64 t; cvta.to.shared.u64 t, %1; cvt.u32.u64 %0, t; }" : "=r"(a) : "l"(p));
    return a;
}
__device__ __forceinline__ void cpa(uint32_t dst, const void* src){
    asm volatile("cp.async.cg.shared.global [%0], [%1], 16;" :: "r"(dst), "l"(src));
}
__device__ __forceinline__ void cpcommit(){ asm volatile("cp.async.commit_group;" ::: "memory"); }
template<int N> __device__ __forceinline__ void cpwait(){ asm volatile("cp.async.wait_group %0;" :: "n"(N) : "memory"); }

__device__ __forceinline__ void ldsm4(uint32_t* r, uint32_t a){
    asm volatile("ldmatrix.sync.aligned.m8n8.x4.shared.b16 {%0,%1,%2,%3}, [%4];"
        : "=r"(r[0]), "=r"(r[1]), "=r"(r[2]), "=r"(r[3]) : "r"(a));
}
__device__ __forceinline__ void mma_bf16(float* d, const uint32_t* a, const uint32_t* b){
    asm volatile(
        "mma.sync.aligned.m16n8k16.row.col.f32.bf16.bf16.f32 "
        "{%0,%1,%2,%3}, {%4,%5,%6,%7}, {%8,%9}, {%0,%1,%2,%3};"
        : "+f"(d[0]), "+f"(d[1]), "+f"(d[2]), "+f"(d[3])
        : "r"(a[0]), "r"(a[1]), "r"(a[2]), "r"(a[3]), "r"(b[0]), "r"(b[1]));
}
__device__ __forceinline__ unsigned short bu(__nv_bfloat16 b){
    return *reinterpret_cast<unsigned short*>(&b);
}

// ---------------- small kernels ----------------
__global__ void k_zero(){ if (threadIdx.x < E_NUM) g_count[threadIdx.x] = 0; }

__global__ void k_router(const float* __restrict__ x, const float* __restrict__ wr){
    int t = blockIdx.x*8 + (threadIdx.x>>5);
    int lane = threadIdx.x & 31;
    if (t >= T_TOK) return;
    float acc[E_NUM];
#pragma unroll
    for (int e=0;e<E_NUM;e++) acc[e]=0.f;
    const float* xr = x + (size_t)t*H_DIM;
    for (int h=lane; h<H_DIM; h+=32){
        float xv = xr[h];
        const float* wrow = wr + (size_t)h*E_NUM;
#pragma unroll
        for (int e=0;e<E_NUM;e++) acc[e] += xv*wrow[e];
    }
#pragma unroll
    for (int off=16; off>0; off>>=1)
#pragma unroll
        for (int e=0;e<E_NUM;e++) acc[e] += __shfl_down_sync(0xFFFFFFFFu, acc[e], off);
    if (lane==0){
        int i0=0; float v0=acc[0];
#pragma unroll
        for (int e=1;e<E_NUM;e++) if (acc[e]>v0){ v0=acc[e]; i0=e; }
        int i1=-1; float v1=-INFINITY;
#pragma unroll
        for (int e=0;e<E_NUM;e++){ if (e==i0) continue; if (acc[e]>v1){ v1=acc[e]; i1=e; } }
        float w0 = 1.f/(1.f+expf(v1-v0));
        float w1 = 1.f - w0;
        int p0 = atomicAdd(&g_count[i0],1); g_tok[i0*T_TOK+p0] = 2*t;
        int p1 = atomicAdd(&g_count[i1],1); g_tok[i1*T_TOK+p1] = 2*t+1;
        g_wgt[2*t]=w0; g_wgt[2*t+1]=w1;
    }
}

__global__ void k_prefix(){
    if (threadIdx.x==0){
        int s=0;
#pragma unroll
        for (int e=0;e<E_NUM;e++){ g_base[e]=s; s+=g_count[e]; }
    }
}

__global__ void __launch_bounds__(256) k_prep(const float* __restrict__ x){
    int e = blockIdx.y, p = blockIdx.x;
    if (p >= g_count[e]) return;
    int r = g_base[e] + p;
    int slot = g_tok[e*T_TOK + p];
    if (threadIdx.x==0) g_rowtok[r] = slot;
    int t = slot >> 1;
    float4 v = ((const float4*)(x + (size_t)t*H_DIM))[threadIdx.x];
    float xs[4] = {v.x, v.y, v.z, v.w};
    unsigned short h[4], l[4];
#pragma unroll
    for (int i=0;i<4;i++){
        __nv_bfloat16 hb = __float2bfloat16_rn(xs[i]);
        h[i] = bu(hb);
        l[i] = bu(__float2bfloat16_rn(xs[i] - __bfloat162float(hb)));
    }
    uint2 hh, ll;
    hh.x = (uint32_t)h[0] | ((uint32_t)h[1]<<16); hh.y = (uint32_t)h[2] | ((uint32_t)h[3]<<16);
    ll.x = (uint32_t)l[0] | ((uint32_t)l[1]<<16); ll.y = (uint32_t)l[2] | ((uint32_t)l[3]<<16);
    *(uint2*)(g_Xhi + (size_t)r*H_DIM + threadIdx.x*4) = hh;
    *(uint2*)(g_Xlo + (size_t)r*H_DIM + threadIdx.x*4) = ll;
}

// transpose-convert: W[e][K][N] fp32 -> Oh/Ol[e][N][K] bf16 hi/lo
__global__ void __launch_bounds__(256) k_convert(const float* __restrict__ W,
                                                 __nv_bfloat16* __restrict__ Oh,
                                                 __nv_bfloat16* __restrict__ Ol,
                                                 int K, int N){
    __shared__ float ts[32][33];
    int e = blockIdx.z;
    int n0 = blockIdx.x*32, k0 = blockIdx.y*32;
    const float* We = W + (size_t)e*K*N;
    int tid = threadIdx.x;
    int r = tid>>3, c4 = (tid&7)*4;
    float4 v = *(const float4*)(We + (size_t)(k0+r)*N + n0 + c4);
    ts[r][c4+0]=v.x; ts[r][c4+1]=v.y; ts[r][c4+2]=v.z; ts[r][c4+3]=v.w;
    __syncthreads();
    unsigned short h[4], l[4];
#pragma unroll
    for (int i=0;i<4;i++){
        float xv = ts[c4+i][r];
        __nv_bfloat16 hb = __float2bfloat16_rn(xv);
        h[i] = bu(hb);
        l[i] = bu(__float2bfloat16_rn(xv - __bfloat162float(hb)));
    }
    size_t ob = ((size_t)e*N + n0 + r)*K + k0 + c4;
    uint2 hh, ll;
    hh.x = (uint32_t)h[0] | ((uint32_t)h[1]<<16); hh.y = (uint32_t)h[2] | ((uint32_t)h[3]<<16);
    ll.x = (uint32_t)l[0] | ((uint32_t)l[1]<<16); ll.y = (uint32_t)l[2] | ((uint32_t)l[3]<<16);
    *(uint2*)(Oh + ob) = hh;
    *(uint2*)(Ol + ob) = ll;
}

// ======================== GEMM 1: gate+up, SiLU epilogue ========================
// CTA 128(M) x 64(N), K chunks of 32, 8 warps (4 M x 2 N), warp tile 32x32.
// SMEM stage: Ah[128][80B] Al | Gh[64][80B] Gl Uh Ul = 40960 B, double buffered.
#define ST_GU 40960
__global__ void __launch_bounds__(256,2) k_gemm_gateup(){
    const int e = blockIdx.z;
    const int cnt = g_count[e];
    const int m0 = blockIdx.x*128;          // m fastest-varying -> weight tiles L2-reused
    if (m0 >= cnt) return;
    const int n0 = blockIdx.y*64;
    const int rowbase = g_base[e] + m0;
    const int vr = min(128, cnt - m0);

    extern __shared__ char sm[];
    uint32_t sb = s2u(sm);

    const int tid = threadIdx.x;
    const int lane = tid & 31, wid = tid >> 5;
    const int wm = wid & 3, wn = wid >> 2;
    const int r0 = lane >> 2;

    // ldmatrix per-lane offsets (80B row stride; conflict-free)
    const uint32_t laneA = (uint32_t)((wm*32 + ((lane>>3)&1)*8 + (lane&7))*80 + (lane>>4)*16);
    const uint32_t laneB = (uint32_t)((wn*32 + (lane>>4)*8 + (lane&7))*80 + ((lane>>3)&1)*16);

    const char* xh = (const char*)g_Xhi + (size_t)rowbase*H_DIM*2;
    const char* xl = (const char*)g_Xlo + (size_t)rowbase*H_DIM*2;
    size_t wo = ((size_t)e*I_DIM + n0)*H_DIM*2;
    const char* gh = (const char*)g_Wg_hi + wo;
    const char* gl = (const char*)g_Wg_lo + wo;
    const char* uh = (const char*)g_Wu_hi + wo;
    const char* ul = (const char*)g_Wu_lo + wo;

    float accG[2][4][4] = {};
    float accU[2][4][4] = {};

    auto load_stage = [&](int kc){
        uint32_t stg = sb + (kc & 1)*ST_GU;
        int kb = kc*64;
#pragma unroll
        for (int c=0;c<4;c++){   // A: 1024 chunks (hi,lo)
            int idx = tid + 256*c;
            int mat = idx >> 9, rem = idx & 511, row = rem >> 2, seg = rem & 3;
            int srow = min(rowbase + row, NSLOT-1) - rowbase;
            const char* s = (mat ? xl : xh) + (size_t)srow*2048 + kb + seg*16;
            cpa(stg + mat*10240 + row*80 + seg*16, s);
        }
#pragma unroll
        for (int c=0;c<4;c++){   // B: 1024 chunks (Gh,Gl,Uh,Ul)
            int idx = tid + 256*c;
            int mat = idx >> 8, rem = idx & 255, row = rem >> 2, seg = rem & 3;
            const char* base = (mat==0) ? gh : (mat==1) ? gl : (mat==2) ? uh : ul;
            const char* s = base + (size_t)row*2048 + kb + seg*16;
            cpa(stg + 20480 + mat*5120 + row*80 + seg*16, s);
        }
        cpcommit();
    };

    auto compute = [&](int kc){
        uint32_t st = sb + (kc & 1)*ST_GU;
        uint32_t aB = st + laneA;
        uint32_t bB = st + 20480 + laneB;
#pragma unroll
        for (int k16=0;k16<2;k16++){
            uint32_t ko = k16*32;
            uint32_t ah[2][4], al[2][4];
            ldsm4(ah[0], aB + ko);
            ldsm4(ah[1], aB + 1280 + ko);
            ldsm4(al[0], aB + 10240 + ko);
            ldsm4(al[1], aB + 11520 + ko);
#pragma unroll
            for (int np=0;np<2;np++){
                uint32_t bgh_[4], bgl_[4], buh_[4], bul_[4];
                uint32_t bo = bB + np*1280 + ko;
                ldsm4(bgh_, bo);
                ldsm4(bgl_, bo + 5120);
                ldsm4(buh_, bo + 10240);
                ldsm4(bul_, bo + 15360);
#pragma unroll
                for (int s=0;s<2;s++){
                    int ni = np*2+s;
#pragma unroll
                    for (int mi=0;mi<2;mi++){
                        mma_bf16(accG[mi][ni], ah[mi], bgh_+2*s);
                        mma_bf16(accG[mi][ni], al[mi], bgh_+2*s);
                        mma_bf16(accG[mi][ni], ah[mi], bgl_+2*s);
                        mma_bf16(accU[mi][ni], ah[mi], buh_+2*s);
                        mma_bf16(accU[mi][ni], al[mi], buh_+2*s);
                        mma_bf16(accU[mi][ni], ah[mi], bul_+2*s);
                    }
                }
            }
        }
    };

    load_stage(0);
    const int NK = H_DIM/32;  // 32
    for (int kc=0; kc<NK; kc++){
        cpwait<0>();
        __syncthreads();
        if (kc+1 < NK) load_stage(kc+1);
        compute(kc);
    }

    // epilogue: a = silu(g)*u -> g_Ahi/g_Alo (hi/lo split)
#pragma unroll
    for (int mi=0;mi<2;mi++)
#pragma unroll
        for (int hf=0;hf<2;hf++){
            int row = wm*32 + mi*16 + r0 + hf*8;
            if (row < vr){
                size_t rb = (size_t)(rowbase + row)*I_DIM;
#pragma unroll
                for (int ni=0;ni<4;ni++){
                    int n = n0 + wn*32 + ni*8 + (lane&3)*2;
                    float g0 = accG[mi][ni][hf*2+0], g1 = accG[mi][ni][hf*2+1];
                    float u0 = accU[mi][ni][hf*2+0], u1 = accU[mi][ni][hf*2+1];
                    float a0 = g0/(1.f+expf(-g0))*u0;
                    float a1 = g1/(1.f+expf(-g1))*u1;
                    __nv_bfloat16 h0=__float2bfloat16_rn(a0), h1=__float2bfloat16_rn(a1);
                    __nv_bfloat16 l0=__float2bfloat16_rn(a0-__bfloat162float(h0));
                    __nv_bfloat16 l1=__float2bfloat16_rn(a1-__bfloat162float(h1));
                    *(uint32_t*)((char*)g_Ahi + (rb+n)*2) = (uint32_t)bu(h0) | ((uint32_t)bu(h1)<<16);
                    *(uint32_t*)((char*)g_Alo + (rb+n)*2) = (uint32_t)bu(l0) | ((uint32_t)bu(l1)<<16);
                }
            }
        }
}

// ======================== GEMM 2: down + bias + weighted combine ========================
// SMEM stage: Ah[128][80B] Al | Wh[64][80B] Wl = 30720 B, double buffered.
#define ST_DN 30720
__global__ void __launch_bounds__(256,2) k_gemm_down(const float* __restrict__ bd,
                                                     float* __restrict__ out){
    const int e = blockIdx.z;
    const int cnt = g_count[e];
    const int m0 = blockIdx.x*128;
    if (m0 >= cnt) return;
    const int n0 = blockIdx.y*64;
    const int rowbase = g_base[e] + m0;
    const int vr = min(128, cnt - m0);

    extern __shared__ char sm[];
    uint32_t sb = s2u(sm);

    const int tid = threadIdx.x;
    const int lane = tid & 31, wid = tid >> 5;
    const int wm = wid & 3, wn = wid >> 2;
    const int r0 = lane >> 2;

    const uint32_t laneA = (uint32_t)((wm*32 + ((lane>>3)&1)*8 + (lane&7))*80 + (lane>>4)*16);
    const uint32_t laneB = (uint32_t)((wn*32 + (lane>>4)*8 + (lane&7))*80 + ((lane>>3)&1)*16);

    const char* ah = (const char*)g_Ahi + (size_t)rowbase*I_DIM*2;
    const char* al = (const char*)g_Alo + (size_t)rowbase*I_DIM*2;
    size_t wo = ((size_t)e*H_DIM + n0)*I_DIM*2;
    const char* wh = (const char*)g_Wd_hi + wo;
    const char* wl = (const char*)g_Wd_lo + wo;
    const size_t strA = (size_t)I_DIM*2;  // 5632

    float acc[2][4][4] = {};

    auto load_stage = [&](int kc){
        uint32_t stg = sb + (kc & 1)*ST_DN;
        int kb = kc*64;
#pragma unroll
        for (int c=0;c<4;c++){
            int idx = tid + 256*c;
            int mat = idx >> 9, rem = idx & 511, row = rem >> 2, seg = rem & 3;
            int srow = min(rowbase + row, NSLOT-1) - rowbase;
            const char* s = (mat ? al : ah) + (size_t)srow*strA + kb + seg*16;
            cpa(stg + mat*10240 + row*80 + seg*16, s);
        }
#pragma unroll
        for (int c=0;c<2;c++){
            int idx = tid + 256*c;
            int mat = idx >> 8, rem = idx & 255, row = rem >> 2, seg = rem & 3;
            const char* s = (mat ? wl : wh) + (size_t)row*strA + kb + seg*16;
            cpa(stg + 20480 + mat*5120 + row*80 + seg*16, s);
        }
        cpcommit();
    };

    auto compute = [&](int kc){
        uint32_t st = sb + (kc & 1)*ST_DN;
        uint32_t aB = st + laneA;
        uint32_t bB = st + 20480 + laneB;
#pragma unroll
        for (int k16=0;k16<2;k16++){
            uint32_t ko = k16*32;
            uint32_t a_h[2][4], a_l[2][4];
            ldsm4(a_h[0], aB + ko);
            ldsm4(a_h[1], aB + 1280 + ko);
            ldsm4(a_l[0], aB + 10240 + ko);
            ldsm4(a_l[1], aB + 11520 + ko);
#pragma unroll
            for (int np=0;np<2;np++){
                uint32_t bwh_[4], bwl_[4];
                uint32_t bo = bB + np*1280 + ko;
                ldsm4(bwh_, bo);
                ldsm4(bwl_, bo + 5120);
#pragma unroll
                for (int s=0;s<2;s++){
                    int ni = np*2+s;
#pragma unroll
                    for (int mi=0;mi<2;mi++){
                        mma_bf16(acc[mi][ni], a_h[mi], bwh_+2*s);
                        mma_bf16(acc[mi][ni], a_l[mi], bwh_+2*s);
                        mma_bf16(acc[mi][ni], a_h[mi], bwl_+2*s);
                    }
                }
            }
        }
    };

    load_stage(0);
    const int NK = I_DIM/32;  // 88
    for (int kc=0; kc<NK; kc++){
        cpwait<0>();
        __syncthreads();
        if (kc+1 < NK) load_stage(kc+1);
        compute(kc);
    }

    // epilogue: out[t] += w * (acc + b_down[e])   (2 commutative adds -> deterministic)
#pragma unroll
    for (int mi=0;mi<2;mi++)
#pragma unroll
        for (int hf=0;hf<2;hf++){
            int row = wm*32 + mi*16 + r0 + hf*8;
            if (row < vr){
                int slot = g_rowtok[rowbase + row];
                float w = g_wgt[slot];
                int t = slot >> 1;
                float* orow = out + (size_t)t*H_DIM;
                const float* brow = bd + (size_t)e*H_DIM;
#pragma unroll
                for (int ni=0;ni<4;ni++){
                    int n = n0 + wn*32 + ni*8 + (lane&3)*2;
                    float v0 = (acc[mi][ni][hf*2+0] + brow[n])   * w;
                    float v1 = (acc[mi][ni][hf*2+1] + brow[n+1]) * w;
                    atomicAdd(&orow[n],   v0);
                    atomicAdd(&orow[n+1], v1);
                }
            }
        }
}

// ---------------- launch ----------------
extern "C" void kernel_launch(void* const* d_in, const int* in_sizes, int n_in,
                              void* d_out, int out_size){
    const float* x  = (const float*)d_in[0];
    const float* wr = (const float*)d_in[1];
    const float* wg = (const float*)d_in[2];
    const float* wu = (const float*)d_in[3];
    const float* wd = (const float*)d_in[4];
    const float* bd = (const float*)d_in[5];
    float* out = (float*)d_out;

    __nv_bfloat16 *wg_hi, *wg_lo, *wu_hi, *wu_lo, *wd_hi, *wd_lo;
    cudaGetSymbolAddress((void**)&wg_hi, g_Wg_hi);
    cudaGetSymbolAddress((void**)&wg_lo, g_Wg_lo);
    cudaGetSymbolAddress((void**)&wu_hi, g_Wu_hi);
    cudaGetSymbolAddress((void**)&wu_lo, g_Wu_lo);
    cudaGetSymbolAddress((void**)&wd_hi, g_Wd_hi);
    cudaGetSymbolAddress((void**)&wd_lo, g_Wd_lo);

    cudaFuncSetAttribute(k_gemm_gateup, cudaFuncAttributeMaxDynamicSharedMemorySize, 2*ST_GU);
    cudaFuncSetAttribute(k_gemm_down,   cudaFuncAttributeMaxDynamicSharedMemorySize, 2*ST_DN);

    cudaMemsetAsync(out, 0, (size_t)out_size * sizeof(float));
    k_zero<<<1,32>>>();
    k_router<<<T_TOK/8, 256>>>(x, wr);
    k_prefix<<<1,32>>>();
    k_prep<<<dim3(T_TOK, E_NUM), 256>>>(x);

    k_convert<<<dim3(I_DIM/32, H_DIM/32, E_NUM), 256>>>(wg, wg_hi, wg_lo, H_DIM, I_DIM);
    k_convert<<<dim3(I_DIM/32, H_DIM/32, E_NUM), 256>>>(wu, wu_hi, wu_lo, H_DIM, I_DIM);
    k_convert<<<dim3(H_DIM/32, I_DIM/32, E_NUM), 256>>>(wd, wd_hi, wd_lo, I_DIM, H_DIM);

    // m-block fastest (grid.x) -> all CTAs in a wave share the same weight tiles (L2 reuse)
    k_gemm_gateup<<<dim3(T_TOK/128, I_DIM/64, E_NUM), 256, 2*ST_GU>>>();
    k_gemm_down  <<<dim3(T_TOK/128, H_DIM/64, E_NUM), 256, 2*ST_DN>>>(bd, out);
}

// round 5
// speedup vs baseline: 3.5167x; 1.0690x over previous
#include <cuda_runtime.h>
#include <cuda_bf16.h>
#include <math.h>
#include <stdint.h>

#define T_TOK 2048
#define H_DIM 1024
#define E_NUM 8
#define I_DIM 2816
#define NSLOT (2*T_TOK)

// ---------------- device scratch ----------------
__device__ int   g_count[E_NUM];
__device__ int   g_base[E_NUM];
__device__ int   g_tok[E_NUM*T_TOK];
__device__ float g_wgt[NSLOT];
__device__ int   g_rowtok[NSLOT];
__device__ __nv_bfloat16 g_Xhi[(size_t)NSLOT*H_DIM];
__device__ __nv_bfloat16 g_Xlo[(size_t)NSLOT*H_DIM];
__device__ __nv_bfloat16 g_Ahi[(size_t)NSLOT*I_DIM];
__device__ __nv_bfloat16 g_Alo[(size_t)NSLOT*I_DIM];

// ---------------- helpers ----------------
__device__ __forceinline__ uint32_t s2u(const void* p){
    uint32_t a;
    asm("{ .reg .u64 t; cvta.to.shared.u64 t, %1; cvt.u32.u64 %0, t; }" : "=r"(a) : "l"(p));
    return a;
}
__device__ __forceinline__ void cpa(uint32_t dst, const void* src){
    asm volatile("cp.async.cg.shared.global [%0], [%1], 16;" :: "r"(dst), "l"(src));
}
__device__ __forceinline__ void cpcommit(){ asm volatile("cp.async.commit_group;" ::: "memory"); }
template<int N> __device__ __forceinline__ void cpwait(){ asm volatile("cp.async.wait_group %0;" :: "n"(N) : "memory"); }

__device__ __forceinline__ void ldsm4(uint32_t* r, uint32_t a){
    asm volatile("ldmatrix.sync.aligned.m8n8.x4.shared.b16 {%0,%1,%2,%3}, [%4];"
        : "=r"(r[0]), "=r"(r[1]), "=r"(r[2]), "=r"(r[3]) : "r"(a));
}
__device__ __forceinline__ void ldsm4t(uint32_t* r, uint32_t a){
    asm volatile("ldmatrix.sync.aligned.m8n8.x4.trans.shared.b16 {%0,%1,%2,%3}, [%4];"
        : "=r"(r[0]), "=r"(r[1]), "=r"(r[2]), "=r"(r[3]) : "r"(a));
}
__device__ __forceinline__ void mma_bf16(float* d, const uint32_t* a, const uint32_t* b){
    asm volatile(
        "mma.sync.aligned.m16n8k16.row.col.f32.bf16.bf16.f32 "
        "{%0,%1,%2,%3}, {%4,%5,%6,%7}, {%8,%9}, {%0,%1,%2,%3};"
        : "+f"(d[0]), "+f"(d[1]), "+f"(d[2]), "+f"(d[3])
        : "r"(a[0]), "r"(a[1]), "r"(a[2]), "r"(a[3]), "r"(b[0]), "r"(b[1]));
}
__device__ __forceinline__ unsigned short bu(__nv_bfloat16 b){
    return *reinterpret_cast<unsigned short*>(&b);
}
__device__ __forceinline__ uint32_t b2u(__nv_bfloat162 v){
    return *reinterpret_cast<uint32_t*>(&v);
}
// split a float4 into packed bf16 hi pairs and lo pairs
__device__ __forceinline__ void splitf4(float4 v, uint32_t& h0, uint32_t& h1,
                                        uint32_t& l0, uint32_t& l1){
    __nv_bfloat162 ha = __floats2bfloat162_rn(v.x, v.y);
    __nv_bfloat162 hb = __floats2bfloat162_rn(v.z, v.w);
    __nv_bfloat162 la = __floats2bfloat162_rn(v.x - __low2float(ha),  v.y - __high2float(ha));
    __nv_bfloat162 lb = __floats2bfloat162_rn(v.z - __low2float(hb),  v.w - __high2float(hb));
    h0 = b2u(ha); h1 = b2u(hb); l0 = b2u(la); l1 = b2u(lb);
}

// ---------------- small kernels ----------------
__global__ void k_zero(){ if (threadIdx.x < E_NUM) g_count[threadIdx.x] = 0; }

__global__ void k_router(const float* __restrict__ x, const float* __restrict__ wr){
    int t = blockIdx.x*8 + (threadIdx.x>>5);
    int lane = threadIdx.x & 31;
    if (t >= T_TOK) return;
    float acc[E_NUM];
#pragma unroll
    for (int e=0;e<E_NUM;e++) acc[e]=0.f;
    const float* xr = x + (size_t)t*H_DIM;
    for (int h=lane; h<H_DIM; h+=32){
        float xv = xr[h];
        const float* wrow = wr + (size_t)h*E_NUM;
#pragma unroll
        for (int e=0;e<E_NUM;e++) acc[e] += xv*wrow[e];
    }
#pragma unroll
    for (int off=16; off>0; off>>=1)
#pragma unroll
        for (int e=0;e<E_NUM;e++) acc[e] += __shfl_down_sync(0xFFFFFFFFu, acc[e], off);
    if (lane==0){
        int i0=0; float v0=acc[0];
#pragma unroll
        for (int e=1;e<E_NUM;e++) if (acc[e]>v0){ v0=acc[e]; i0=e; }
        int i1=-1; float v1=-INFINITY;
#pragma unroll
        for (int e=0;e<E_NUM;e++){ if (e==i0) continue; if (acc[e]>v1){ v1=acc[e]; i1=e; } }
        float w0 = 1.f/(1.f+expf(v1-v0));
        float w1 = 1.f - w0;
        int p0 = atomicAdd(&g_count[i0],1); g_tok[i0*T_TOK+p0] = 2*t;
        int p1 = atomicAdd(&g_count[i1],1); g_tok[i1*T_TOK+p1] = 2*t+1;
        g_wgt[2*t]=w0; g_wgt[2*t+1]=w1;
    }
}

__global__ void k_prefix(){
    if (threadIdx.x==0){
        int s=0;
#pragma unroll
        for (int e=0;e<E_NUM;e++){ g_base[e]=s; s+=g_count[e]; }
    }
}

__global__ void __launch_bounds__(256) k_prep(const float* __restrict__ x){
    int e = blockIdx.y, p = blockIdx.x;
    if (p >= g_count[e]) return;
    int r = g_base[e] + p;
    int slot = g_tok[e*T_TOK + p];
    if (threadIdx.x==0) g_rowtok[r] = slot;
    int t = slot >> 1;
    float4 v = ((const float4*)(x + (size_t)t*H_DIM))[threadIdx.x];
    uint32_t h0,h1,l0,l1;
    splitf4(v, h0,h1,l0,l1);
    *(uint2*)(g_Xhi + (size_t)r*H_DIM + threadIdx.x*4) = make_uint2(h0,h1);
    *(uint2*)(g_Xlo + (size_t)r*H_DIM + threadIdx.x*4) = make_uint2(l0,l1);
}

// ======================== GEMM 1: gate+up (fused fp32 weight convert) ========================
// CTA 128(M) x 64(N), K chunks of 32, 8 warps (4M x 2N), warp tile 32x32.
// SMEM layout:
//   [0, 40960)        A stages: s*20480; hi+0, lo+10240; row stride 80B
//   [40960, 77824)    B bf16 stages: 40960 + s*18432; Gh+0, Gl+4608, Uh+9216, Ul+13824;
//                     layout [k=32][n=64], row stride 144B
//   [77824, 95232)    B fp32 buffer: gate+0, up+8704; [k=32][n=64] f32, row stride 272B
#define GU_SMEM 95232
__global__ void __launch_bounds__(256,2) k_gemm_gateup(const float* __restrict__ wg,
                                                       const float* __restrict__ wu){
    const int e = blockIdx.z;
    const int cnt = g_count[e];
    const int m0 = blockIdx.x*128;
    if (m0 >= cnt) return;
    const int n0 = blockIdx.y*64;
    const int rowbase = g_base[e] + m0;
    const int vr = min(128, cnt - m0);

    extern __shared__ char sm[];
    uint32_t sb = s2u(sm);

    const int tid = threadIdx.x;
    const int lane = tid & 31, wid = tid >> 5;
    const int wm = wid & 3, wn = wid >> 2;
    const int r0 = lane >> 2;

    const uint32_t laneA  = (uint32_t)((wm*32 + ((lane>>3)&1)*8 + (lane&7))*80 + (lane>>4)*16);
    const uint32_t laneBT = (uint32_t)((lane&15)*144 + (lane>>4)*16);

    const char* xh = (const char*)g_Xhi + (size_t)rowbase*H_DIM*2;
    const char* xl = (const char*)g_Xlo + (size_t)rowbase*H_DIM*2;
    const float* wg_p = wg + (size_t)e*H_DIM*I_DIM + n0;
    const float* wu_p = wu + (size_t)e*H_DIM*I_DIM + n0;

    float accG[2][4][4] = {};
    float accU[2][4][4] = {};

    auto issue_stage = [&](int kc){
        uint32_t astg = sb + (kc & 1)*20480;
        int kb = kc*64;
#pragma unroll
        for (int c=0;c<4;c++){   // A bf16: 1024 x 16B
            int idx = tid + 256*c;
            int mat = idx >> 9, rem = idx & 511, row = rem >> 2, seg = rem & 3;
            int srow = min(rowbase + row, NSLOT-1) - rowbase;
            const char* s = (mat ? xl : xh) + (size_t)srow*2048 + kb + seg*16;
            cpa(astg + mat*10240 + row*80 + seg*16, s);
        }
        int kr = kc*32;
#pragma unroll
        for (int c=0;c<4;c++){   // B fp32: 1024 x 16B (gate, up)
            int idx = tid + 256*c;
            int mat = idx >> 9, rem = idx & 511, row = rem >> 4, seg = rem & 15;
            const float* s = (mat ? wu_p : wg_p) + (size_t)(kr + row)*I_DIM + seg*4;
            cpa(sb + 77824 + mat*8704 + row*272 + seg*16, s);
        }
        cpcommit();
    };

    auto convert = [&](int kc){
        char* bbn = sm + 40960 + (kc & 1)*18432;
#pragma unroll
        for (int m=0;m<2;m++){
#pragma unroll
            for (int p=0;p<2;p++){
                int row = (tid>>4) + p*16;
                int c4  = (tid & 15);
                float4 v = *(const float4*)(sm + 77824 + m*8704 + row*272 + c4*16);
                uint32_t h0,h1,l0,l1;
                splitf4(v, h0,h1,l0,l1);
                char* dh = bbn + m*9216 + row*144 + c4*8;
                *(uint2*)dh          = make_uint2(h0,h1);
                *(uint2*)(dh + 4608) = make_uint2(l0,l1);
            }
        }
    };

    auto compute = [&](int kc){
        uint32_t aB = sb + (kc & 1)*20480 + laneA;
        uint32_t bBase = sb + 40960 + (kc & 1)*18432 + laneBT + (wn*64);
#pragma unroll
        for (int k16=0;k16<2;k16++){
            uint32_t ko = k16*32;
            uint32_t ah[2][4], al[2][4];
            ldsm4(ah[0], aB + ko);
            ldsm4(ah[1], aB + 1280 + ko);
            ldsm4(al[0], aB + 10240 + ko);
            ldsm4(al[1], aB + 11520 + ko);
#pragma unroll
            for (int np=0;np<2;np++){
                uint32_t bgh_[4], bgl_[4], buh_[4], bul_[4];
                uint32_t bo = bBase + k16*2304 + np*32;
                ldsm4t(bgh_, bo);
                ldsm4t(bgl_, bo + 4608);
                ldsm4t(buh_, bo + 9216);
                ldsm4t(bul_, bo + 13824);
#pragma unroll
                for (int s=0;s<2;s++){
                    int ni = np*2+s;
#pragma unroll
                    for (int mi=0;mi<2;mi++){
                        mma_bf16(accG[mi][ni], ah[mi], bgh_+2*s);
                        mma_bf16(accG[mi][ni], al[mi], bgh_+2*s);
                        mma_bf16(accG[mi][ni], ah[mi], bgl_+2*s);
                        mma_bf16(accU[mi][ni], ah[mi], buh_+2*s);
                        mma_bf16(accU[mi][ni], al[mi], buh_+2*s);
                        mma_bf16(accU[mi][ni], ah[mi], bul_+2*s);
                    }
                }
            }
        }
    };

    // prologue
    issue_stage(0);
    cpwait<0>(); __syncthreads();
    convert(0);
    __syncthreads();

    const int NK = H_DIM/32;  // 32
    for (int kc=0; kc<NK; kc++){
        if (kc+1 < NK) issue_stage(kc+1);
        compute(kc);
        if (kc+1 < NK){
            cpwait<0>(); __syncthreads();
            convert(kc+1);
            __syncthreads();
        }
    }

    // epilogue: a = silu(g)*u -> g_Ahi/g_Alo (hi/lo split)
#pragma unroll
    for (int mi=0;mi<2;mi++)
#pragma unroll
        for (int hf=0;hf<2;hf++){
            int row = wm*32 + mi*16 + r0 + hf*8;
            if (row < vr){
                size_t rb = (size_t)(rowbase + row)*I_DIM;
#pragma unroll
                for (int ni=0;ni<4;ni++){
                    int n = n0 + wn*32 + ni*8 + (lane&3)*2;
                    float g0 = accG[mi][ni][hf*2+0], g1 = accG[mi][ni][hf*2+1];
                    float u0 = accU[mi][ni][hf*2+0], u1 = accU[mi][ni][hf*2+1];
                    float a0 = g0/(1.f+expf(-g0))*u0;
                    float a1 = g1/(1.f+expf(-g1))*u1;
                    __nv_bfloat16 h0=__float2bfloat16_rn(a0), h1=__float2bfloat16_rn(a1);
                    __nv_bfloat16 l0=__float2bfloat16_rn(a0-__bfloat162float(h0));
                    __nv_bfloat16 l1=__float2bfloat16_rn(a1-__bfloat162float(h1));
                    *(uint32_t*)((char*)g_Ahi + (rb+n)*2) = (uint32_t)bu(h0) | ((uint32_t)bu(h1)<<16);
                    *(uint32_t*)((char*)g_Alo + (rb+n)*2) = (uint32_t)bu(l0) | ((uint32_t)bu(l1)<<16);
                }
            }
        }
}

// ======================== GEMM 2: down + bias + weighted combine (fused convert) ==============
// SMEM layout:
//   [0, 40960)        A stages (g_Ahi/g_Alo), as above
//   [40960, 59392)    B bf16 stages: 40960 + s*9216; Wh+0, Wl+4608; [k=32][n=64], stride 144B
//   [59392, 68096)    B fp32 buffer: [32][64] f32, stride 272B
#define DN_SMEM 68096
__global__ void __launch_bounds__(256,2) k_gemm_down(const float* __restrict__ wd,
                                                     const float* __restrict__ bd,
                                                     float* __restrict__ out){
    const int e = blockIdx.z;
    const int cnt = g_count[e];
    const int m0 = blockIdx.x*128;
    if (m0 >= cnt) return;
    const int n0 = blockIdx.y*64;
    const int rowbase = g_base[e] + m0;
    const int vr = min(128, cnt - m0);

    extern __shared__ char sm[];
    uint32_t sb = s2u(sm);

    const int tid = threadIdx.x;
    const int lane = tid & 31, wid = tid >> 5;
    const int wm = wid & 3, wn = wid >> 2;
    const int r0 = lane >> 2;

    const uint32_t laneA  = (uint32_t)((wm*32 + ((lane>>3)&1)*8 + (lane&7))*80 + (lane>>4)*16);
    const uint32_t laneBT = (uint32_t)((lane&15)*144 + (lane>>4)*16);

    const char* ah = (const char*)g_Ahi + (size_t)rowbase*I_DIM*2;
    const char* al = (const char*)g_Alo + (size_t)rowbase*I_DIM*2;
    const float* wd_p = wd + (size_t)e*I_DIM*H_DIM + n0;
    const size_t strA = (size_t)I_DIM*2;  // 5632

    float acc[2][4][4] = {};

    auto issue_stage = [&](int kc){
        uint32_t astg = sb + (kc & 1)*20480;
        int kb = kc*64;
#pragma unroll
        for (int c=0;c<4;c++){
            int idx = tid + 256*c;
            int mat = idx >> 9, rem = idx & 511, row = rem >> 2, seg = rem & 3;
            int srow = min(rowbase + row, NSLOT-1) - rowbase;
            const char* s = (mat ? al : ah) + (size_t)srow*strA + kb + seg*16;
            cpa(astg + mat*10240 + row*80 + seg*16, s);
        }
        int kr = kc*32;
#pragma unroll
        for (int c=0;c<2;c++){   // B fp32: 512 x 16B
            int idx = tid + 256*c;
            int row = idx >> 4, seg = idx & 15;
            const float* s = wd_p + (size_t)(kr + row)*H_DIM + seg*4;
            cpa(sb + 59392 + row*272 + seg*16, s);
        }
        cpcommit();
    };

    auto convert = [&](int kc){
        char* bbn = sm + 40960 + (kc & 1)*9216;
#pragma unroll
        for (int p=0;p<2;p++){
            int row = (tid>>4) + p*16;
            int c4  = (tid & 15);
            float4 v = *(const float4*)(sm + 59392 + row*272 + c4*16);
            uint32_t h0,h1,l0,l1;
            splitf4(v, h0,h1,l0,l1);
            char* dh = bbn + row*144 + c4*8;
            *(uint2*)dh          = make_uint2(h0,h1);
            *(uint2*)(dh + 4608) = make_uint2(l0,l1);
        }
    };

    auto compute = [&](int kc){
        uint32_t aB = sb + (kc & 1)*20480 + laneA;
        uint32_t bBase = sb + 40960 + (kc & 1)*9216 + laneBT + (wn*64);
#pragma unroll
        for (int k16=0;k16<2;k16++){
            uint32_t ah_[2][4], al_[2][4];
            uint32_t ko = k16*32;
            ldsm4(ah_[0], aB + ko);
            ldsm4(ah_[1], aB + 1280 + ko);
            ldsm4(al_[0], aB + 10240 + ko);
            ldsm4(al_[1], aB + 11520 + ko);
#pragma unroll
            for (int np=0;np<2;np++){
                uint32_t bwh_[4], bwl_[4];
                uint32_t bo = bBase + k16*2304 + np*32;
                ldsm4t(bwh_, bo);
                ldsm4t(bwl_, bo + 4608);
#pragma unroll
                for (int s=0;s<2;s++){
                    int ni = np*2+s;
#pragma unroll
                    for (int mi=0;mi<2;mi++){
                        mma_bf16(acc[mi][ni], ah_[mi], bwh_+2*s);
                        mma_bf16(acc[mi][ni], al_[mi], bwh_+2*s);
                        mma_bf16(acc[mi][ni], ah_[mi], bwl_+2*s);
                    }
                }
            }
        }
    };

    issue_stage(0);
    cpwait<0>(); __syncthreads();
    convert(0);
    __syncthreads();

    const int NK = I_DIM/32;  // 88
    for (int kc=0; kc<NK; kc++){
        if (kc+1 < NK) issue_stage(kc+1);
        compute(kc);
        if (kc+1 < NK){
            cpwait<0>(); __syncthreads();
            convert(kc+1);
            __syncthreads();
        }
    }

    // epilogue: out[t] += w * (acc + b_down[e])   (2 commutative adds -> deterministic)
#pragma unroll
    for (int mi=0;mi<2;mi++)
#pragma unroll
        for (int hf=0;hf<2;hf++){
            int row = wm*32 + mi*16 + r0 + hf*8;
            if (row < vr){
                int slot = g_rowtok[rowbase + row];
                float w = g_wgt[slot];
                int t = slot >> 1;
                float* orow = out + (size_t)t*H_DIM;
                const float* brow = bd + (size_t)e*H_DIM;
#pragma unroll
                for (int ni=0;ni<4;ni++){
                    int n = n0 + wn*32 + ni*8 + (lane&3)*2;
                    float v0 = (acc[mi][ni][hf*2+0] + brow[n])   * w;
                    float v1 = (acc[mi][ni][hf*2+1] + brow[n+1]) * w;
                    atomicAdd(&orow[n],   v0);
                    atomicAdd(&orow[n+1], v1);
                }
            }
        }
}

// ---------------- launch ----------------
extern "C" void kernel_launch(void* const* d_in, const int* in_sizes, int n_in,
                              void* d_out, int out_size){
    const float* x  = (const float*)d_in[0];
    const float* wr = (const float*)d_in[1];
    const float* wg = (const float*)d_in[2];
    const float* wu = (const float*)d_in[3];
    const float* wd = (const float*)d_in[4];
    const float* bd = (const float*)d_in[5];
    float* out = (float*)d_out;

    cudaFuncSetAttribute(k_gemm_gateup, cudaFuncAttributeMaxDynamicSharedMemorySize, GU_SMEM);
    cudaFuncSetAttribute(k_gemm_down,   cudaFuncAttributeMaxDynamicSharedMemorySize, DN_SMEM);

    cudaMemsetAsync(out, 0, (size_t)out_size * sizeof(float));
    k_zero<<<1,32>>>();
    k_router<<<T_TOK/8, 256>>>(x, wr);
    k_prefix<<<1,32>>>();
    k_prep<<<dim3(T_TOK, E_NUM), 256>>>(x);

    // m-block fastest (grid.x) -> wave shares weight tiles in L2
    k_gemm_gateup<<<dim3(T_TOK/128, I_DIM/64, E_NUM), 256, GU_SMEM>>>(wg, wu);
    k_gemm_down  <<<dim3(T_TOK/128, H_DIM/64, E_NUM), 256, DN_SMEM>>>(wd, bd, out);
}

// round 6
// speedup vs baseline: 3.6292x; 1.0320x over previous
#include <cuda_runtime.h>
#include <cuda_bf16.h>
#include <math.h>
#include <stdint.h>

#define T_TOK 2048
#define H_DIM 1024
#define E_NUM 8
#define I_DIM 2816
#define NSLOT (2*T_TOK)

// ---------------- device scratch ----------------
__device__ int   g_count[E_NUM];
__device__ int   g_base[E_NUM];
__device__ int   g_tok[E_NUM*T_TOK];
__device__ float g_wgt[NSLOT];
__device__ int   g_rowtok[NSLOT];
__device__ __nv_bfloat16 g_Xhi[(size_t)NSLOT*H_DIM];
__device__ __nv_bfloat16 g_Xlo[(size_t)NSLOT*H_DIM];
__device__ __nv_bfloat16 g_Ahi[(size_t)NSLOT*I_DIM];
__device__ __nv_bfloat16 g_Alo[(size_t)NSLOT*I_DIM];

// ---------------- helpers ----------------
__device__ __forceinline__ uint32_t s2u(const void* p){
    uint32_t a;
    asm("{ .reg .u64 t; cvta.to.shared.u64 t, %1; cvt.u32.u64 %0, t; }" : "=r"(a) : "l"(p));
    return a;
}
__device__ __forceinline__ void cpa(uint32_t dst, const void* src){
    asm volatile("cp.async.cg.shared.global [%0], [%1], 16;" :: "r"(dst), "l"(src));
}
__device__ __forceinline__ void cpcommit(){ asm volatile("cp.async.commit_group;" ::: "memory"); }
template<int N> __device__ __forceinline__ void cpwait(){ asm volatile("cp.async.wait_group %0;" :: "n"(N) : "memory"); }

__device__ __forceinline__ void ldsm4(uint32_t* r, uint32_t a){
    asm volatile("ldmatrix.sync.aligned.m8n8.x4.shared.b16 {%0,%1,%2,%3}, [%4];"
        : "=r"(r[0]), "=r"(r[1]), "=r"(r[2]), "=r"(r[3]) : "r"(a));
}
__device__ __forceinline__ void ldsm4t(uint32_t* r, uint32_t a){
    asm volatile("ldmatrix.sync.aligned.m8n8.x4.trans.shared.b16 {%0,%1,%2,%3}, [%4];"
        : "=r"(r[0]), "=r"(r[1]), "=r"(r[2]), "=r"(r[3]) : "r"(a));
}
__device__ __forceinline__ void mma_bf16(float* d, const uint32_t* a, const uint32_t* b){
    asm volatile(
        "mma.sync.aligned.m16n8k16.row.col.f32.bf16.bf16.f32 "
        "{%0,%1,%2,%3}, {%4,%5,%6,%7}, {%8,%9}, {%0,%1,%2,%3};"
        : "+f"(d[0]), "+f"(d[1]), "+f"(d[2]), "+f"(d[3])
        : "r"(a[0]), "r"(a[1]), "r"(a[2]), "r"(a[3]), "r"(b[0]), "r"(b[1]));
}
__device__ __forceinline__ unsigned short bu(__nv_bfloat16 b){
    return *reinterpret_cast<unsigned short*>(&b);
}
__device__ __forceinline__ uint32_t b2u(__nv_bfloat162 v){
    return *reinterpret_cast<uint32_t*>(&v);
}
__device__ __forceinline__ void splitf4(float4 v, uint32_t& h0, uint32_t& h1,
                                        uint32_t& l0, uint32_t& l1){
    __nv_bfloat162 ha = __floats2bfloat162_rn(v.x, v.y);
    __nv_bfloat162 hb = __floats2bfloat162_rn(v.z, v.w);
    __nv_bfloat162 la = __floats2bfloat162_rn(v.x - __low2float(ha),  v.y - __high2float(ha));
    __nv_bfloat162 lb = __floats2bfloat162_rn(v.z - __low2float(hb),  v.w - __high2float(hb));
    h0 = b2u(ha); h1 = b2u(hb); l0 = b2u(la); l1 = b2u(lb);
}

// ---------------- small kernels ----------------
__global__ void k_zero(){ if (threadIdx.x < E_NUM) g_count[threadIdx.x] = 0; }

__global__ void k_router(const float* __restrict__ x, const float* __restrict__ wr){
    int t = blockIdx.x*8 + (threadIdx.x>>5);
    int lane = threadIdx.x & 31;
    if (t >= T_TOK) return;
    float acc[E_NUM];
#pragma unroll
    for (int e=0;e<E_NUM;e++) acc[e]=0.f;
    const float* xr = x + (size_t)t*H_DIM;
    for (int h=lane; h<H_DIM; h+=32){
        float xv = xr[h];
        const float* wrow = wr + (size_t)h*E_NUM;
#pragma unroll
        for (int e=0;e<E_NUM;e++) acc[e] += xv*wrow[e];
    }
#pragma unroll
    for (int off=16; off>0; off>>=1)
#pragma unroll
        for (int e=0;e<E_NUM;e++) acc[e] += __shfl_down_sync(0xFFFFFFFFu, acc[e], off);
    if (lane==0){
        int i0=0; float v0=acc[0];
#pragma unroll
        for (int e=1;e<E_NUM;e++) if (acc[e]>v0){ v0=acc[e]; i0=e; }
        int i1=-1; float v1=-INFINITY;
#pragma unroll
        for (int e=0;e<E_NUM;e++){ if (e==i0) continue; if (acc[e]>v1){ v1=acc[e]; i1=e; } }
        float w0 = 1.f/(1.f+expf(v1-v0));
        float w1 = 1.f - w0;
        int p0 = atomicAdd(&g_count[i0],1); g_tok[i0*T_TOK+p0] = 2*t;
        int p1 = atomicAdd(&g_count[i1],1); g_tok[i1*T_TOK+p1] = 2*t+1;
        g_wgt[2*t]=w0; g_wgt[2*t+1]=w1;
    }
}

__global__ void k_prefix(){
    if (threadIdx.x==0){
        int s=0;
#pragma unroll
        for (int e=0;e<E_NUM;e++){ g_base[e]=s; s+=g_count[e]; }
    }
}

__global__ void __launch_bounds__(256) k_prep(const float* __restrict__ x){
    int e = blockIdx.y, p = blockIdx.x;
    if (p >= g_count[e]) return;
    int r = g_base[e] + p;
    int slot = g_tok[e*T_TOK + p];
    if (threadIdx.x==0) g_rowtok[r] = slot;
    int t = slot >> 1;
    float4 v = ((const float4*)(x + (size_t)t*H_DIM))[threadIdx.x];
    uint32_t h0,h1,l0,l1;
    splitf4(v, h0,h1,l0,l1);
    *(uint2*)(g_Xhi + (size_t)r*H_DIM + threadIdx.x*4) = make_uint2(h0,h1);
    *(uint2*)(g_Xlo + (size_t)r*H_DIM + threadIdx.x*4) = make_uint2(l0,l1);
}

// ======================== GEMM 1: gate+up (fused fp32 weight convert) ========================
// CTA 128(M) x 64(N), K chunks of 32, 8 warps (4M x 2N), warp tile 32x32.
// SMEM layout:
//   [0, 40960)          A stages: s*20480; hi+0, lo+10240; row stride 80B
//   [40960, 77824)      B bf16 stages: 40960 + s*18432; Gh+0, Gl+4608, Uh+9216, Ul+13824;
//                       layout [k=32][n=64], row stride 144B
//   [77824, 112640)     B fp32 stages: 77824 + s*17408; gate+0, up+8704; stride 272B
#define GU_SMEM 112640
__global__ void __launch_bounds__(256,2) k_gemm_gateup(const float* __restrict__ wg,
                                                       const float* __restrict__ wu){
    const int e = blockIdx.z;
    const int cnt = g_count[e];
    const int m0 = blockIdx.x*128;
    if (m0 >= cnt) return;
    const int n0 = blockIdx.y*64;
    const int rowbase = g_base[e] + m0;
    const int vr = min(128, cnt - m0);

    extern __shared__ char sm[];
    uint32_t sb = s2u(sm);

    const int tid = threadIdx.x;
    const int lane = tid & 31, wid = tid >> 5;
    const int wm = wid & 3, wn = wid >> 2;
    const int r0 = lane >> 2;

    const uint32_t laneA  = (uint32_t)((wm*32 + ((lane>>3)&1)*8 + (lane&7))*80 + (lane>>4)*16);
    const uint32_t laneBT = (uint32_t)((lane&15)*144 + (lane>>4)*16);

    const char* xh = (const char*)g_Xhi + (size_t)rowbase*H_DIM*2;
    const char* xl = (const char*)g_Xlo + (size_t)rowbase*H_DIM*2;
    const float* wg_p = wg + (size_t)e*H_DIM*I_DIM + n0;
    const float* wu_p = wu + (size_t)e*H_DIM*I_DIM + n0;

    // per-thread fixed row/col for B fp32 staging (load mapping == convert mapping)
    const int brow = tid >> 4;         // 0..15
    const int bseg = tid & 15;         // 0..15 (16B columns)

    float accG[2][4][4] = {};
    float accU[2][4][4] = {};

    auto issue_stage = [&](int kc){
        uint32_t astg = sb + (kc & 1)*20480;
        int kb = kc*64;
#pragma unroll
        for (int c=0;c<4;c++){   // A bf16: 1024 x 16B
            int idx = tid + 256*c;
            int mat = idx >> 9, rem = idx & 511, row = rem >> 2, seg = rem & 3;
            int srow = min(rowbase + row, NSLOT-1) - rowbase;
            const char* s = (mat ? xl : xh) + (size_t)srow*2048 + kb + seg*16;
            cpa(astg + mat*10240 + row*80 + seg*16, s);
        }
        int kr = kc*32;
        uint32_t fstg = sb + 77824 + (kc & 1)*17408;
#pragma unroll
        for (int c=0;c<4;c++){   // B fp32 (own-data mapping): m=c>>1, p=c&1
            int m = c >> 1, p = c & 1;
            int row = brow + p*16;
            const float* s = (m ? wu_p : wg_p) + (size_t)(kr + row)*I_DIM + bseg*4;
            cpa(fstg + m*8704 + row*272 + bseg*16, s);
        }
        cpcommit();
    };

    // each thread converts exactly the fp32 bytes it cp.async'd (visible after cpwait)
    auto convert = [&](int kc){
        const char* fb = sm + 77824 + (kc & 1)*17408;
        char* bbn = sm + 40960 + (kc & 1)*18432;
#pragma unroll
        for (int m=0;m<2;m++){
#pragma unroll
            for (int p=0;p<2;p++){
                int row = brow + p*16;
                float4 v = *(const float4*)(fb + m*8704 + row*272 + bseg*16);
                uint32_t h0,h1,l0,l1;
                splitf4(v, h0,h1,l0,l1);
                char* dh = bbn + m*9216 + row*144 + bseg*8;
                *(uint2*)dh          = make_uint2(h0,h1);
                *(uint2*)(dh + 4608) = make_uint2(l0,l1);
            }
        }
    };

    auto compute = [&](int kc){
        uint32_t aB = sb + (kc & 1)*20480 + laneA;
        uint32_t bBase = sb + 40960 + (kc & 1)*18432 + laneBT + (wn*64);
#pragma unroll
        for (int k16=0;k16<2;k16++){
            uint32_t ko = k16*32;
            uint32_t ah[2][4], al[2][4];
            ldsm4(ah[0], aB + ko);
            ldsm4(ah[1], aB + 1280 + ko);
            ldsm4(al[0], aB + 10240 + ko);
            ldsm4(al[1], aB + 11520 + ko);
#pragma unroll
            for (int np=0;np<2;np++){
                uint32_t bgh_[4], bgl_[4], buh_[4], bul_[4];
                uint32_t bo = bBase + k16*2304 + np*32;
                ldsm4t(bgh_, bo);
                ldsm4t(bgl_, bo + 4608);
                ldsm4t(buh_, bo + 9216);
                ldsm4t(bul_, bo + 13824);
#pragma unroll
                for (int s=0;s<2;s++){
                    int ni = np*2+s;
#pragma unroll
                    for (int mi=0;mi<2;mi++){
                        mma_bf16(accG[mi][ni], ah[mi], bgh_+2*s);
                        mma_bf16(accG[mi][ni], al[mi], bgh_+2*s);
                        mma_bf16(accG[mi][ni], ah[mi], bgl_+2*s);
                        mma_bf16(accU[mi][ni], ah[mi], buh_+2*s);
                        mma_bf16(accU[mi][ni], al[mi], buh_+2*s);
                        mma_bf16(accU[mi][ni], ah[mi], bul_+2*s);
                    }
                }
            }
        }
    };

    // prologue: stage 0 in flight -> convert own data -> publish
    issue_stage(0);
    cpwait<0>();
    convert(0);
    __syncthreads();

    const int NK = H_DIM/32;  // 32
    for (int kc=0; kc<NK; kc++){
        if (kc+1 < NK) issue_stage(kc+1);   // loads fly during compute
        compute(kc);
        if (kc+1 < NK){
            cpwait<0>();                     // ~free: had full compute phase
            convert(kc+1);                   // own-data, no barrier needed first
        }
        __syncthreads();                     // single barrier per chunk
    }

    // epilogue: a = silu(g)*u -> g_Ahi/g_Alo (hi/lo split)
#pragma unroll
    for (int mi=0;mi<2;mi++)
#pragma unroll
        for (int hf=0;hf<2;hf++){
            int row = wm*32 + mi*16 + r0 + hf*8;
            if (row < vr){
                size_t rb = (size_t)(rowbase + row)*I_DIM;
#pragma unroll
                for (int ni=0;ni<4;ni++){
                    int n = n0 + wn*32 + ni*8 + (lane&3)*2;
                    float g0 = accG[mi][ni][hf*2+0], g1 = accG[mi][ni][hf*2+1];
                    float u0 = accU[mi][ni][hf*2+0], u1 = accU[mi][ni][hf*2+1];
                    float a0 = g0/(1.f+expf(-g0))*u0;
                    float a1 = g1/(1.f+expf(-g1))*u1;
                    __nv_bfloat16 h0=__float2bfloat16_rn(a0), h1=__float2bfloat16_rn(a1);
                    __nv_bfloat16 l0=__float2bfloat16_rn(a0-__bfloat162float(h0));
                    __nv_bfloat16 l1=__float2bfloat16_rn(a1-__bfloat162float(h1));
                    *(uint32_t*)((char*)g_Ahi + (rb+n)*2) = (uint32_t)bu(h0) | ((uint32_t)bu(h1)<<16);
                    *(uint32_t*)((char*)g_Alo + (rb+n)*2) = (uint32_t)bu(l0) | ((uint32_t)bu(l1)<<16);
                }
            }
        }
}

// ======================== GEMM 2: down + bias + weighted combine (fused convert) ==============
// SMEM layout:
//   [0, 40960)        A stages (g_Ahi/g_Alo)
//   [40960, 59392)    B bf16 stages: 40960 + s*9216; Wh+0, Wl+4608; stride 144B
//   [59392, 76800)    B fp32 stages: 59392 + s*8704; stride 272B
#define DN_SMEM 76800
__global__ void __launch_bounds__(256,2) k_gemm_down(const float* __restrict__ wd,
                                                     const float* __restrict__ bd,
                                                     float* __restrict__ out){
    const int e = blockIdx.z;
    const int cnt = g_count[e];
    const int m0 = blockIdx.x*128;
    if (m0 >= cnt) return;
    const int n0 = blockIdx.y*64;
    const int rowbase = g_base[e] + m0;
    const int vr = min(128, cnt - m0);

    extern __shared__ char sm[];
    uint32_t sb = s2u(sm);

    const int tid = threadIdx.x;
    const int lane = tid & 31, wid = tid >> 5;
    const int wm = wid & 3, wn = wid >> 2;
    const int r0 = lane >> 2;

    const uint32_t laneA  = (uint32_t)((wm*32 + ((lane>>3)&1)*8 + (lane&7))*80 + (lane>>4)*16);
    const uint32_t laneBT = (uint32_t)((lane&15)*144 + (lane>>4)*16);

    const char* ah = (const char*)g_Ahi + (size_t)rowbase*I_DIM*2;
    const char* al = (const char*)g_Alo + (size_t)rowbase*I_DIM*2;
    const float* wd_p = wd + (size_t)e*I_DIM*H_DIM + n0;
    const size_t strA = (size_t)I_DIM*2;  // 5632

    const int brow = tid >> 4;
    const int bseg = tid & 15;

    float acc[2][4][4] = {};

    auto issue_stage = [&](int kc){
        uint32_t astg = sb + (kc & 1)*20480;
        int kb = kc*64;
#pragma unroll
        for (int c=0;c<4;c++){
            int idx = tid + 256*c;
            int mat = idx >> 9, rem = idx & 511, row = rem >> 2, seg = rem & 3;
            int srow = min(rowbase + row, NSLOT-1) - rowbase;
            const char* s = (mat ? al : ah) + (size_t)srow*strA + kb + seg*16;
            cpa(astg + mat*10240 + row*80 + seg*16, s);
        }
        int kr = kc*32;
        uint32_t fstg = sb + 59392 + (kc & 1)*8704;
#pragma unroll
        for (int p=0;p<2;p++){
            int row = brow + p*16;
            const float* s = wd_p + (size_t)(kr + row)*H_DIM + bseg*4;
            cpa(fstg + row*272 + bseg*16, s);
        }
        cpcommit();
    };

    auto convert = [&](int kc){
        const char* fb = sm + 59392 + (kc & 1)*8704;
        char* bbn = sm + 40960 + (kc & 1)*9216;
#pragma unroll
        for (int p=0;p<2;p++){
            int row = brow + p*16;
            float4 v = *(const float4*)(fb + row*272 + bseg*16);
            uint32_t h0,h1,l0,l1;
            splitf4(v, h0,h1,l0,l1);
            char* dh = bbn + row*144 + bseg*8;
            *(uint2*)dh          = make_uint2(h0,h1);
            *(uint2*)(dh + 4608) = make_uint2(l0,l1);
        }
    };

    auto compute = [&](int kc){
        uint32_t aB = sb + (kc & 1)*20480 + laneA;
        uint32_t bBase = sb + 40960 + (kc & 1)*9216 + laneBT + (wn*64);
#pragma unroll
        for (int k16=0;k16<2;k16++){
            uint32_t ah_[2][4], al_[2][4];
            uint32_t ko = k16*32;
            ldsm4(ah_[0], aB + ko);
            ldsm4(ah_[1], aB + 1280 + ko);
            ldsm4(al_[0], aB + 10240 + ko);
            ldsm4(al_[1], aB + 11520 + ko);
#pragma unroll
            for (int np=0;np<2;np++){
                uint32_t bwh_[4], bwl_[4];
                uint32_t bo = bBase + k16*2304 + np*32;
                ldsm4t(bwh_, bo);
                ldsm4t(bwl_, bo + 4608);
#pragma unroll
                for (int s=0;s<2;s++){
                    int ni = np*2+s;
#pragma unroll
                    for (int mi=0;mi<2;mi++){
                        mma_bf16(acc[mi][ni], ah_[mi], bwh_+2*s);
                        mma_bf16(acc[mi][ni], al_[mi], bwh_+2*s);
                        mma_bf16(acc[mi][ni], ah_[mi], bwl_+2*s);
                    }
                }
            }
        }
    };

    issue_stage(0);
    cpwait<0>();
    convert(0);
    __syncthreads();

    const int NK = I_DIM/32;  // 88
    for (int kc=0; kc<NK; kc++){
        if (kc+1 < NK) issue_stage(kc+1);
        compute(kc);
        if (kc+1 < NK){
            cpwait<0>();
            convert(kc+1);
        }
        __syncthreads();
    }

    // epilogue: out[t] += w * (acc + b_down[e])   (2 commutative adds -> deterministic)
#pragma unroll
    for (int mi=0;mi<2;mi++)
#pragma unroll
        for (int hf=0;hf<2;hf++){
            int row = wm*32 + mi*16 + r0 + hf*8;
            if (row < vr){
                int slot = g_rowtok[rowbase + row];
                float w = g_wgt[slot];
                int t = slot >> 1;
                float* orow = out + (size_t)t*H_DIM;
                const float* brow_ = bd + (size_t)e*H_DIM;
#pragma unroll
                for (int ni=0;ni<4;ni++){
                    int n = n0 + wn*32 + ni*8 + (lane&3)*2;
                    float v0 = (acc[mi][ni][hf*2+0] + brow_[n])   * w;
                    float v1 = (acc[mi][ni][hf*2+1] + brow_[n+1]) * w;
                    atomicAdd(&orow[n],   v0);
                    atomicAdd(&orow[n+1], v1);
                }
            }
        }
}

// ---------------- launch ----------------
extern "C" void kernel_launch(void* const* d_in, const int* in_sizes, int n_in,
                              void* d_out, int out_size){
    const float* x  = (const float*)d_in[0];
    const float* wr = (const float*)d_in[1];
    const float* wg = (const float*)d_in[2];
    const float* wu = (const float*)d_in[3];
    const float* wd = (const float*)d_in[4];
    const float* bd = (const float*)d_in[5];
    float* out = (float*)d_out;

    cudaFuncSetAttribute(k_gemm_gateup, cudaFuncAttributeMaxDynamicSharedMemorySize, GU_SMEM);
    cudaFuncSetAttribute(k_gemm_down,   cudaFuncAttributeMaxDynamicSharedMemorySize, DN_SMEM);

    cudaMemsetAsync(out, 0, (size_t)out_size * sizeof(float));
    k_zero<<<1,32>>>();
    k_router<<<T_TOK/8, 256>>>(x, wr);
    k_prefix<<<1,32>>>();
    k_prep<<<dim3(T_TOK, E_NUM), 256>>>(x);

    // m-block fastest (grid.x) -> wave shares weight tiles in L2
    k_gemm_gateup<<<dim3(T_TOK/128, I_DIM/64, E_NUM), 256, GU_SMEM>>>(wg, wu);
    k_gemm_down  <<<dim3(T_TOK/128, H_DIM/64, E_NUM), 256, DN_SMEM>>>(wd, bd, out);
}

// round 7
// speedup vs baseline: 3.6966x; 1.0186x over previous
#include <cuda_runtime.h>
#include <cuda_bf16.h>
#include <math.h>
#include <stdint.h>

#define T_TOK 2048
#define H_DIM 1024
#define E_NUM 8
#define I_DIM 2816
#define NSLOT (2*T_TOK)

// ---------------- device scratch ----------------
__device__ int   g_count[E_NUM];
__device__ int   g_base[E_NUM];
__device__ int   g_tok[E_NUM*T_TOK];
__device__ float g_wgt[NSLOT];
__device__ int   g_rowtok[NSLOT];
__device__ __nv_bfloat16 g_Xhi[(size_t)NSLOT*H_DIM];
__device__ __nv_bfloat16 g_Xlo[(size_t)NSLOT*H_DIM];
__device__ __nv_bfloat16 g_Ahi[(size_t)NSLOT*I_DIM];
__device__ __nv_bfloat16 g_Alo[(size_t)NSLOT*I_DIM];

// ---------------- helpers ----------------
__device__ __forceinline__ uint32_t s2u(const void* p){
    uint32_t a;
    asm("{ .reg .u64 t; cvta.to.shared.u64 t, %1; cvt.u32.u64 %0, t; }" : "=r"(a) : "l"(p));
    return a;
}
__device__ __forceinline__ void cpa(uint32_t dst, const void* src){
    asm volatile("cp.async.cg.shared.global [%0], [%1], 16;" :: "r"(dst), "l"(src));
}
__device__ __forceinline__ void cpcommit(){ asm volatile("cp.async.commit_group;" ::: "memory"); }
template<int N> __device__ __forceinline__ void cpwait(){ asm volatile("cp.async.wait_group %0;" :: "n"(N) : "memory"); }

__device__ __forceinline__ void ldsm4(uint32_t* r, uint32_t a){
    asm volatile("ldmatrix.sync.aligned.m8n8.x4.shared.b16 {%0,%1,%2,%3}, [%4];"
        : "=r"(r[0]), "=r"(r[1]), "=r"(r[2]), "=r"(r[3]) : "r"(a));
}
__device__ __forceinline__ void ldsm4t(uint32_t* r, uint32_t a){
    asm volatile("ldmatrix.sync.aligned.m8n8.x4.trans.shared.b16 {%0,%1,%2,%3}, [%4];"
        : "=r"(r[0]), "=r"(r[1]), "=r"(r[2]), "=r"(r[3]) : "r"(a));
}
__device__ __forceinline__ void mma_bf16(float* d, const uint32_t* a, const uint32_t* b){
    asm volatile(
        "mma.sync.aligned.m16n8k16.row.col.f32.bf16.bf16.f32 "
        "{%0,%1,%2,%3}, {%4,%5,%6,%7}, {%8,%9}, {%0,%1,%2,%3};"
        : "+f"(d[0]), "+f"(d[1]), "+f"(d[2]), "+f"(d[3])
        : "r"(a[0]), "r"(a[1]), "r"(a[2]), "r"(a[3]), "r"(b[0]), "r"(b[1]));
}
__device__ __forceinline__ unsigned short bu(__nv_bfloat16 b){
    return *reinterpret_cast<unsigned short*>(&b);
}
__device__ __forceinline__ uint32_t b2u(__nv_bfloat162 v){
    return *reinterpret_cast<uint32_t*>(&v);
}
__device__ __forceinline__ void splitf4(float4 v, uint32_t& h0, uint32_t& h1,
                                        uint32_t& l0, uint32_t& l1){
    __nv_bfloat162 ha = __floats2bfloat162_rn(v.x, v.y);
    __nv_bfloat162 hb = __floats2bfloat162_rn(v.z, v.w);
    __nv_bfloat162 la = __floats2bfloat162_rn(v.x - __low2float(ha),  v.y - __high2float(ha));
    __nv_bfloat162 lb = __floats2bfloat162_rn(v.z - __low2float(hb),  v.w - __high2float(hb));
    h0 = b2u(ha); h1 = b2u(hb); l0 = b2u(la); l1 = b2u(lb);
}

// ---------------- small kernels ----------------
__global__ void k_zero(){ if (threadIdx.x < E_NUM) g_count[threadIdx.x] = 0; }

__global__ void k_router(const float* __restrict__ x, const float* __restrict__ wr){
    int t = blockIdx.x*8 + (threadIdx.x>>5);
    int lane = threadIdx.x & 31;
    if (t >= T_TOK) return;
    float acc[E_NUM];
#pragma unroll
    for (int e=0;e<E_NUM;e++) acc[e]=0.f;
    const float* xr = x + (size_t)t*H_DIM;
    for (int h=lane; h<H_DIM; h+=32){
        float xv = xr[h];
        const float* wrow = wr + (size_t)h*E_NUM;
#pragma unroll
        for (int e=0;e<E_NUM;e++) acc[e] += xv*wrow[e];
    }
#pragma unroll
    for (int off=16; off>0; off>>=1)
#pragma unroll
        for (int e=0;e<E_NUM;e++) acc[e] += __shfl_down_sync(0xFFFFFFFFu, acc[e], off);
    if (lane==0){
        int i0=0; float v0=acc[0];
#pragma unroll
        for (int e=1;e<E_NUM;e++) if (acc[e]>v0){ v0=acc[e]; i0=e; }
        int i1=-1; float v1=-INFINITY;
#pragma unroll
        for (int e=0;e<E_NUM;e++){ if (e==i0) continue; if (acc[e]>v1){ v1=acc[e]; i1=e; } }
        float w0 = 1.f/(1.f+expf(v1-v0));
        float w1 = 1.f - w0;
        int p0 = atomicAdd(&g_count[i0],1); g_tok[i0*T_TOK+p0] = 2*t;
        int p1 = atomicAdd(&g_count[i1],1); g_tok[i1*T_TOK+p1] = 2*t+1;
        g_wgt[2*t]=w0; g_wgt[2*t+1]=w1;
    }
}

__global__ void k_prefix(){
    if (threadIdx.x==0){
        int s=0;
#pragma unroll
        for (int e=0;e<E_NUM;e++){ g_base[e]=s; s+=g_count[e]; }
    }
}

__global__ void __launch_bounds__(256) k_prep(const float* __restrict__ x){
    int e = blockIdx.y, p = blockIdx.x;
    if (p >= g_count[e]) return;
    int r = g_base[e] + p;
    int slot = g_tok[e*T_TOK + p];
    if (threadIdx.x==0) g_rowtok[r] = slot;
    int t = slot >> 1;
    float4 v = ((const float4*)(x + (size_t)t*H_DIM))[threadIdx.x];
    uint32_t h0,h1,l0,l1;
    splitf4(v, h0,h1,l0,l1);
    *(uint2*)(g_Xhi + (size_t)r*H_DIM + threadIdx.x*4) = make_uint2(h0,h1);
    *(uint2*)(g_Xlo + (size_t)r*H_DIM + threadIdx.x*4) = make_uint2(l0,l1);
}

// ======================== GEMM 1: gate+up (fused fp32 weight convert) ========================
// CTA 128(M) x 64(N), K chunks of 32, 8 warps (4M x 2N), warp tile 32x32.
// SMEM layout:
//   [0, 40960)          A stages: s*20480; hi+0, lo+10240; row stride 80B
//   [40960, 77824)      B bf16 stages: 40960 + s*18432; Gh+0, Gl+4608, Uh+9216, Ul+13824;
//                       layout [k=32][n=64], row stride 144B
//   [77824, 112640)     B fp32 stages: 77824 + s*17408; gate+0, up+8704; stride 272B
#define GU_SMEM 112640
__global__ void __launch_bounds__(256,2) k_gemm_gateup(const float* __restrict__ wg,
                                                       const float* __restrict__ wu){
    const int e = blockIdx.z;
    const int cnt = g_count[e];
    const int m0 = blockIdx.x*128;
    if (m0 >= cnt) return;
    const int n0 = blockIdx.y*64;
    const int rowbase = g_base[e] + m0;
    const int vr = min(128, cnt - m0);

    extern __shared__ char sm[];
    uint32_t sb = s2u(sm);

    const int tid = threadIdx.x;
    const int lane = tid & 31, wid = tid >> 5;
    const int wm = wid & 3, wn = wid >> 2;
    const int r0 = lane >> 2;

    const uint32_t laneA  = (uint32_t)((wm*32 + ((lane>>3)&1)*8 + (lane&7))*80 + (lane>>4)*16);
    const uint32_t laneBT = (uint32_t)((lane&15)*144 + (lane>>4)*16);

    const char* xh = (const char*)g_Xhi + (size_t)rowbase*H_DIM*2;
    const char* xl = (const char*)g_Xlo + (size_t)rowbase*H_DIM*2;
    const float* wg_p = wg + (size_t)e*H_DIM*I_DIM + n0;
    const float* wu_p = wu + (size_t)e*H_DIM*I_DIM + n0;

    const int brow = tid >> 4;         // 0..15
    const int bseg = tid & 15;         // 0..15 (16B columns)

    float accG[2][4][4] = {};
    float accU[2][4][4] = {};

    auto issue_stage = [&](int kc){
        uint32_t astg = sb + (kc & 1)*20480;
        int kb = kc*64;
#pragma unroll
        for (int c=0;c<4;c++){   // A bf16: 1024 x 16B
            int idx = tid + 256*c;
            int mat = idx >> 9, rem = idx & 511, row = rem >> 2, seg = rem & 3;
            int srow = min(rowbase + row, NSLOT-1) - rowbase;
            const char* s = (mat ? xl : xh) + (size_t)srow*2048 + kb + seg*16;
            cpa(astg + mat*10240 + row*80 + seg*16, s);
        }
        int kr = kc*32;
        uint32_t fstg = sb + 77824 + (kc & 1)*17408;
#pragma unroll
        for (int c=0;c<4;c++){   // B fp32 (own-data mapping)
            int m = c >> 1, p = c & 1;
            int row = brow + p*16;
            const float* s = (m ? wu_p : wg_p) + (size_t)(kr + row)*I_DIM + bseg*4;
            cpa(fstg + m*8704 + row*272 + bseg*16, s);
        }
        cpcommit();
    };

    auto convert = [&](int kc){
        const char* fb = sm + 77824 + (kc & 1)*17408;
        char* bbn = sm + 40960 + (kc & 1)*18432;
#pragma unroll
        for (int m=0;m<2;m++){
#pragma unroll
            for (int p=0;p<2;p++){
                int row = brow + p*16;
                float4 v = *(const float4*)(fb + m*8704 + row*272 + bseg*16);
                uint32_t h0,h1,l0,l1;
                splitf4(v, h0,h1,l0,l1);
                char* dh = bbn + m*9216 + row*144 + bseg*8;
                *(uint2*)dh          = make_uint2(h0,h1);
                *(uint2*)(dh + 4608) = make_uint2(l0,l1);
            }
        }
    };

    // register-lean compute: only ONE matrix pair of B frags live at a time
    auto compute = [&](int kc){
        uint32_t aB = sb + (kc & 1)*20480 + laneA;
        uint32_t bBase = sb + 40960 + (kc & 1)*18432 + laneBT + (wn*64);
#pragma unroll
        for (int k16=0;k16<2;k16++){
            uint32_t ko = k16*32;
            uint32_t ah[2][4], al[2][4];
            ldsm4(ah[0], aB + ko);
            ldsm4(ah[1], aB + 1280 + ko);
            ldsm4(al[0], aB + 10240 + ko);
            ldsm4(al[1], aB + 11520 + ko);
#pragma unroll
            for (int np=0;np<2;np++){
                uint32_t bo = bBase + k16*2304 + np*32;
                {   // gate pair (hi, lo) -- 8 live B regs
                    uint32_t bh_[4], bl_[4];
                    ldsm4t(bh_, bo);
                    ldsm4t(bl_, bo + 4608);
#pragma unroll
                    for (int s=0;s<2;s++){
                        int ni = np*2+s;
#pragma unroll
                        for (int mi=0;mi<2;mi++){
                            mma_bf16(accG[mi][ni], ah[mi], bh_+2*s);
                            mma_bf16(accG[mi][ni], al[mi], bh_+2*s);
                            mma_bf16(accG[mi][ni], ah[mi], bl_+2*s);
                        }
                    }
                }
                {   // up pair (hi, lo) -- reuses the 8 B regs
                    uint32_t bh_[4], bl_[4];
                    ldsm4t(bh_, bo + 9216);
                    ldsm4t(bl_, bo + 13824);
#pragma unroll
                    for (int s=0;s<2;s++){
                        int ni = np*2+s;
#pragma unroll
                        for (int mi=0;mi<2;mi++){
                            mma_bf16(accU[mi][ni], ah[mi], bh_+2*s);
                            mma_bf16(accU[mi][ni], al[mi], bh_+2*s);
                            mma_bf16(accU[mi][ni], ah[mi], bl_+2*s);
                        }
                    }
                }
            }
        }
    };

    issue_stage(0);
    cpwait<0>();
    convert(0);
    __syncthreads();

    const int NK = H_DIM/32;  // 32
    for (int kc=0; kc<NK; kc++){
        if (kc+1 < NK) issue_stage(kc+1);
        compute(kc);
        if (kc+1 < NK){
            cpwait<0>();
            convert(kc+1);
        }
        __syncthreads();
    }

    // epilogue: a = silu(g)*u -> g_Ahi/g_Alo (hi/lo split)
#pragma unroll
    for (int mi=0;mi<2;mi++)
#pragma unroll
        for (int hf=0;hf<2;hf++){
            int row = wm*32 + mi*16 + r0 + hf*8;
            if (row < vr){
                size_t rb = (size_t)(rowbase + row)*I_DIM;
#pragma unroll
                for (int ni=0;ni<4;ni++){
                    int n = n0 + wn*32 + ni*8 + (lane&3)*2;
                    float g0 = accG[mi][ni][hf*2+0], g1 = accG[mi][ni][hf*2+1];
                    float u0 = accU[mi][ni][hf*2+0], u1 = accU[mi][ni][hf*2+1];
                    float a0 = g0/(1.f+expf(-g0))*u0;
                    float a1 = g1/(1.f+expf(-g1))*u1;
                    __nv_bfloat16 h0=__float2bfloat16_rn(a0), h1=__float2bfloat16_rn(a1);
                    __nv_bfloat16 l0=__float2bfloat16_rn(a0-__bfloat162float(h0));
                    __nv_bfloat16 l1=__float2bfloat16_rn(a1-__bfloat162float(h1));
                    *(uint32_t*)((char*)g_Ahi + (rb+n)*2) = (uint32_t)bu(h0) | ((uint32_t)bu(h1)<<16);
                    *(uint32_t*)((char*)g_Alo + (rb+n)*2) = (uint32_t)bu(l0) | ((uint32_t)bu(l1)<<16);
                }
            }
        }
}

// ======================== GEMM 2: down + bias + weighted combine (fused convert) ==============
// SMEM layout:
//   [0, 40960)        A stages (g_Ahi/g_Alo)
//   [40960, 59392)    B bf16 stages: 40960 + s*9216; Wh+0, Wl+4608; stride 144B
//   [59392, 76800)    B fp32 stages: 59392 + s*8704; stride 272B
#define DN_SMEM 76800
__global__ void __launch_bounds__(256,2) k_gemm_down(const float* __restrict__ wd,
                                                     const float* __restrict__ bd,
                                                     float* __restrict__ out){
    const int e = blockIdx.z;
    const int cnt = g_count[e];
    const int m0 = blockIdx.x*128;
    if (m0 >= cnt) return;
    const int n0 = blockIdx.y*64;
    const int rowbase = g_base[e] + m0;
    const int vr = min(128, cnt - m0);

    extern __shared__ char sm[];
    uint32_t sb = s2u(sm);

    const int tid = threadIdx.x;
    const int lane = tid & 31, wid = tid >> 5;
    const int wm = wid & 3, wn = wid >> 2;
    const int r0 = lane >> 2;

    const uint32_t laneA  = (uint32_t)((wm*32 + ((lane>>3)&1)*8 + (lane&7))*80 + (lane>>4)*16);
    const uint32_t laneBT = (uint32_t)((lane&15)*144 + (lane>>4)*16);

    const char* ah = (const char*)g_Ahi + (size_t)rowbase*I_DIM*2;
    const char* al = (const char*)g_Alo + (size_t)rowbase*I_DIM*2;
    const float* wd_p = wd + (size_t)e*I_DIM*H_DIM + n0;
    const size_t strA = (size_t)I_DIM*2;  // 5632

    const int brow = tid >> 4;
    const int bseg = tid & 15;

    float acc[2][4][4] = {};

    auto issue_stage = [&](int kc){
        uint32_t astg = sb + (kc & 1)*20480;
        int kb = kc*64;
#pragma unroll
        for (int c=0;c<4;c++){
            int idx = tid + 256*c;
            int mat = idx >> 9, rem = idx & 511, row = rem >> 2, seg = rem & 3;
            int srow = min(rowbase + row, NSLOT-1) - rowbase;
            const char* s = (mat ? al : ah) + (size_t)srow*strA + kb + seg*16;
            cpa(astg + mat*10240 + row*80 + seg*16, s);
        }
        int kr = kc*32;
        uint32_t fstg = sb + 59392 + (kc & 1)*8704;
#pragma unroll
        for (int p=0;p<2;p++){
            int row = brow + p*16;
            const float* s = wd_p + (size_t)(kr + row)*H_DIM + bseg*4;
            cpa(fstg + row*272 + bseg*16, s);
        }
        cpcommit();
    };

    auto convert = [&](int kc){
        const char* fb = sm + 59392 + (kc & 1)*8704;
        char* bbn = sm + 40960 + (kc & 1)*9216;
#pragma unroll
        for (int p=0;p<2;p++){
            int row = brow + p*16;
            float4 v = *(const float4*)(fb + row*272 + bseg*16);
            uint32_t h0,h1,l0,l1;
            splitf4(v, h0,h1,l0,l1);
            char* dh = bbn + row*144 + bseg*8;
            *(uint2*)dh          = make_uint2(h0,h1);
            *(uint2*)(dh + 4608) = make_uint2(l0,l1);
        }
    };

    auto compute = [&](int kc){
        uint32_t aB = sb + (kc & 1)*20480 + laneA;
        uint32_t bBase = sb + 40960 + (kc & 1)*9216 + laneBT + (wn*64);
#pragma unroll
        for (int k16=0;k16<2;k16++){
            uint32_t ah_[2][4], al_[2][4];
            uint32_t ko = k16*32;
            ldsm4(ah_[0], aB + ko);
            ldsm4(ah_[1], aB + 1280 + ko);
            ldsm4(al_[0], aB + 10240 + ko);
            ldsm4(al_[1], aB + 11520 + ko);
#pragma unroll
            for (int np=0;np<2;np++){
                uint32_t bh_[4], bl_[4];
                uint32_t bo = bBase + k16*2304 + np*32;
                ldsm4t(bh_, bo);
                ldsm4t(bl_, bo + 4608);
#pragma unroll
                for (int s=0;s<2;s++){
                    int ni = np*2+s;
#pragma unroll
                    for (int mi=0;mi<2;mi++){
                        mma_bf16(acc[mi][ni], ah_[mi], bh_+2*s);
                        mma_bf16(acc[mi][ni], al_[mi], bh_+2*s);
                        mma_bf16(acc[mi][ni], ah_[mi], bl_+2*s);
                    }
                }
            }
        }
    };

    issue_stage(0);
    cpwait<0>();
    convert(0);
    __syncthreads();

    const int NK = I_DIM/32;  // 88
    for (int kc=0; kc<NK; kc++){
        if (kc+1 < NK) issue_stage(kc+1);
        compute(kc);
        if (kc+1 < NK){
            cpwait<0>();
            convert(kc+1);
        }
        __syncthreads();
    }

    // epilogue: out[t] += w * (acc + b_down[e])   (2 commutative adds -> deterministic)
#pragma unroll
    for (int mi=0;mi<2;mi++)
#pragma unroll
        for (int hf=0;hf<2;hf++){
            int row = wm*32 + mi*16 + r0 + hf*8;
            if (row < vr){
                int slot = g_rowtok[rowbase + row];
                float w = g_wgt[slot];
                int t = slot >> 1;
                float* orow = out + (size_t)t*H_DIM;
                const float* brow_ = bd + (size_t)e*H_DIM;
#pragma unroll
                for (int ni=0;ni<4;ni++){
                    int n = n0 + wn*32 + ni*8 + (lane&3)*2;
                    float v0 = (acc[mi][ni][hf*2+0] + brow_[n])   * w;
                    float v1 = (acc[mi][ni][hf*2+1] + brow_[n+1]) * w;
                    atomicAdd(&orow[n],   v0);
                    atomicAdd(&orow[n+1], v1);
                }
            }
        }
}

// ---------------- launch ----------------
extern "C" void kernel_launch(void* const* d_in, const int* in_sizes, int n_in,
                              void* d_out, int out_size){
    const float* x  = (const float*)d_in[0];
    const float* wr = (const float*)d_in[1];
    const float* wg = (const float*)d_in[2];
    const float* wu = (const float*)d_in[3];
    const float* wd = (const float*)d_in[4];
    const float* bd = (const float*)d_in[5];
    float* out = (float*)d_out;

    cudaFuncSetAttribute(k_gemm_gateup, cudaFuncAttributeMaxDynamicSharedMemorySize, GU_SMEM);
    cudaFuncSetAttribute(k_gemm_down,   cudaFuncAttributeMaxDynamicSharedMemorySize, DN_SMEM);

    cudaMemsetAsync(out, 0, (size_t)out_size * sizeof(float));
    k_zero<<<1,32>>>();
    k_router<<<T_TOK/8, 256>>>(x, wr);
    k_prefix<<<1,32>>>();
    k_prep<<<dim3(T_TOK, E_NUM), 256>>>(x);

    k_gemm_gateup<<<dim3(T_TOK/128, I_DIM/64, E_NUM), 256, GU_SMEM>>>(wg, wu);
    k_gemm_down  <<<dim3(T_TOK/128, H_DIM/64, E_NUM), 256, DN_SMEM>>>(wd, bd, out);
}

// round 8
// speedup vs baseline: 4.4628x; 1.2073x over previous
#include <cuda_runtime.h>
#include <cuda_fp16.h>
#include <math.h>
#include <stdint.h>

#define T_TOK 2048
#define H_DIM 1024
#define E_NUM 8
#define I_DIM 2816
#define NSLOT (2*T_TOK)

// ---------------- device scratch ----------------
__device__ int   g_count[E_NUM];
__device__ int   g_base[E_NUM];
__device__ int   g_tok[E_NUM*T_TOK];
__device__ float g_wgt[NSLOT];
__device__ int   g_rowtok[NSLOT];
__device__ __half g_Xhi[(size_t)NSLOT*H_DIM];
__device__ __half g_Xlo[(size_t)NSLOT*H_DIM];
__device__ __half g_Ahi[(size_t)NSLOT*I_DIM];
__device__ __half g_Alo[(size_t)NSLOT*I_DIM];

// ---------------- helpers ----------------
__device__ __forceinline__ uint32_t s2u(const void* p){
    uint32_t a;
    asm("{ .reg .u64 t; cvta.to.shared.u64 t, %1; cvt.u32.u64 %0, t; }" : "=r"(a) : "l"(p));
    return a;
}
__device__ __forceinline__ void cpa(uint32_t dst, const void* src){
    asm volatile("cp.async.cg.shared.global [%0], [%1], 16;" :: "r"(dst), "l"(src));
}
__device__ __forceinline__ void cpcommit(){ asm volatile("cp.async.commit_group;" ::: "memory"); }
template<int N> __device__ __forceinline__ void cpwait(){ asm volatile("cp.async.wait_group %0;" :: "n"(N) : "memory"); }

__device__ __forceinline__ void ldsm4(uint32_t* r, uint32_t a){
    asm volatile("ldmatrix.sync.aligned.m8n8.x4.shared.b16 {%0,%1,%2,%3}, [%4];"
        : "=r"(r[0]), "=r"(r[1]), "=r"(r[2]), "=r"(r[3]) : "r"(a));
}
__device__ __forceinline__ void ldsm4t(uint32_t* r, uint32_t a){
    asm volatile("ldmatrix.sync.aligned.m8n8.x4.trans.shared.b16 {%0,%1,%2,%3}, [%4];"
        : "=r"(r[0]), "=r"(r[1]), "=r"(r[2]), "=r"(r[3]) : "r"(a));
}
__device__ __forceinline__ void mma_f16(float* d, const uint32_t* a, const uint32_t* b){
    asm volatile(
        "mma.sync.aligned.m16n8k16.row.col.f32.f16.f16.f32 "
        "{%0,%1,%2,%3}, {%4,%5,%6,%7}, {%8,%9}, {%0,%1,%2,%3};"
        : "+f"(d[0]), "+f"(d[1]), "+f"(d[2]), "+f"(d[3])
        : "r"(a[0]), "r"(a[1]), "r"(a[2]), "r"(a[3]), "r"(b[0]), "r"(b[1]));
}
__device__ __forceinline__ unsigned short hu(__half b){
    return *reinterpret_cast<unsigned short*>(&b);
}
__device__ __forceinline__ uint32_t h2u(__half2 v){
    return *reinterpret_cast<uint32_t*>(&v);
}
// split a float4 into packed fp16 hi pairs and lo pairs
__device__ __forceinline__ void splitf4h(float4 v, uint32_t& h0, uint32_t& h1,
                                         uint32_t& l0, uint32_t& l1){
    __half2 ha = __floats2half2_rn(v.x, v.y);
    __half2 hb = __floats2half2_rn(v.z, v.w);
    __half2 la = __floats2half2_rn(v.x - __low2float(ha),  v.y - __high2float(ha));
    __half2 lb = __floats2half2_rn(v.z - __low2float(hb),  v.w - __high2float(hb));
    h0 = h2u(ha); h1 = h2u(hb); l0 = h2u(la); l1 = h2u(lb);
}
// round a float4 to packed fp16 pairs (hi only)
__device__ __forceinline__ void roundf4h(float4 v, uint32_t& h0, uint32_t& h1){
    h0 = h2u(__floats2half2_rn(v.x, v.y));
    h1 = h2u(__floats2half2_rn(v.z, v.w));
}

// ---------------- small kernels ----------------
__global__ void k_zero(){ if (threadIdx.x < E_NUM) g_count[threadIdx.x] = 0; }

__global__ void k_router(const float* __restrict__ x, const float* __restrict__ wr){
    int t = blockIdx.x*8 + (threadIdx.x>>5);
    int lane = threadIdx.x & 31;
    if (t >= T_TOK) return;
    float acc[E_NUM];
#pragma unroll
    for (int e=0;e<E_NUM;e++) acc[e]=0.f;
    const float* xr = x + (size_t)t*H_DIM;
    for (int h=lane; h<H_DIM; h+=32){
        float xv = xr[h];
        const float* wrow = wr + (size_t)h*E_NUM;
#pragma unroll
        for (int e=0;e<E_NUM;e++) acc[e] += xv*wrow[e];
    }
#pragma unroll
    for (int off=16; off>0; off>>=1)
#pragma unroll
        for (int e=0;e<E_NUM;e++) acc[e] += __shfl_down_sync(0xFFFFFFFFu, acc[e], off);
    if (lane==0){
        int i0=0; float v0=acc[0];
#pragma unroll
        for (int e=1;e<E_NUM;e++) if (acc[e]>v0){ v0=acc[e]; i0=e; }
        int i1=-1; float v1=-INFINITY;
#pragma unroll
        for (int e=0;e<E_NUM;e++){ if (e==i0) continue; if (acc[e]>v1){ v1=acc[e]; i1=e; } }
        float w0 = 1.f/(1.f+expf(v1-v0));
        float w1 = 1.f - w0;
        int p0 = atomicAdd(&g_count[i0],1); g_tok[i0*T_TOK+p0] = 2*t;
        int p1 = atomicAdd(&g_count[i1],1); g_tok[i1*T_TOK+p1] = 2*t+1;
        g_wgt[2*t]=w0; g_wgt[2*t+1]=w1;
    }
}

__global__ void k_prefix(){
    if (threadIdx.x==0){
        int s=0;
#pragma unroll
        for (int e=0;e<E_NUM;e++){ g_base[e]=s; s+=g_count[e]; }
    }
}

__global__ void __launch_bounds__(256) k_prep(const float* __restrict__ x){
    int e = blockIdx.y, p = blockIdx.x;
    if (p >= g_count[e]) return;
    int r = g_base[e] + p;
    int slot = g_tok[e*T_TOK + p];
    if (threadIdx.x==0) g_rowtok[r] = slot;
    int t = slot >> 1;
    float4 v = ((const float4*)(x + (size_t)t*H_DIM))[threadIdx.x];
    uint32_t h0,h1,l0,l1;
    splitf4h(v, h0,h1,l0,l1);
    *(uint2*)(g_Xhi + (size_t)r*H_DIM + threadIdx.x*4) = make_uint2(h0,h1);
    *(uint2*)(g_Xlo + (size_t)r*H_DIM + threadIdx.x*4) = make_uint2(l0,l1);
}

// ======================== GEMM 1: gate+up (fused fp32->fp16 weight round) ========================
// CTA 128(M) x 64(N), K chunks of 32, 8 warps (4M x 2N), warp tile 32x32.
// SMEM layout:
//   [0, 40960)        A stages: s*20480; hi+0, lo+10240; row stride 80B
//   [40960, 59392)    B fp16 stages: 40960 + s*9216; G+0, U+4608; [k=32][n=64], stride 144B
//   [59392, 94208)    B fp32 stages: 59392 + s*17408; gate+0, up+8704; stride 272B
#define GU_SMEM 94208
__global__ void __launch_bounds__(256,2) k_gemm_gateup(const float* __restrict__ wg,
                                                       const float* __restrict__ wu){
    const int e = blockIdx.z;
    const int cnt = g_count[e];
    const int m0 = blockIdx.x*128;
    if (m0 >= cnt) return;
    const int n0 = blockIdx.y*64;
    const int rowbase = g_base[e] + m0;
    const int vr = min(128, cnt - m0);

    extern __shared__ char sm[];
    uint32_t sb = s2u(sm);

    const int tid = threadIdx.x;
    const int lane = tid & 31, wid = tid >> 5;
    const int wm = wid & 3, wn = wid >> 2;
    const int r0 = lane >> 2;

    const uint32_t laneA  = (uint32_t)((wm*32 + ((lane>>3)&1)*8 + (lane&7))*80 + (lane>>4)*16);
    const uint32_t laneBT = (uint32_t)((lane&15)*144 + (lane>>4)*16);

    const char* xh = (const char*)g_Xhi + (size_t)rowbase*H_DIM*2;
    const char* xl = (const char*)g_Xlo + (size_t)rowbase*H_DIM*2;
    const float* wg_p = wg + (size_t)e*H_DIM*I_DIM + n0;
    const float* wu_p = wu + (size_t)e*H_DIM*I_DIM + n0;

    const int brow = tid >> 4;         // 0..15
    const int bseg = tid & 15;         // 0..15 (16B columns)

    float accG[2][4][4] = {};
    float accU[2][4][4] = {};

    auto issue_stage = [&](int kc){
        uint32_t astg = sb + (kc & 1)*20480;
        int kb = kc*64;
#pragma unroll
        for (int c=0;c<4;c++){   // A fp16: 1024 x 16B
            int idx = tid + 256*c;
            int mat = idx >> 9, rem = idx & 511, row = rem >> 2, seg = rem & 3;
            int srow = min(rowbase + row, NSLOT-1) - rowbase;
            const char* s = (mat ? xl : xh) + (size_t)srow*2048 + kb + seg*16;
            cpa(astg + mat*10240 + row*80 + seg*16, s);
        }
        int kr = kc*32;
        uint32_t fstg = sb + 59392 + (kc & 1)*17408;
#pragma unroll
        for (int c=0;c<4;c++){   // B fp32 (own-data mapping)
            int m = c >> 1, p = c & 1;
            int row = brow + p*16;
            const float* s = (m ? wu_p : wg_p) + (size_t)(kr + row)*I_DIM + bseg*4;
            cpa(fstg + m*8704 + row*272 + bseg*16, s);
        }
        cpcommit();
    };

    // each thread rounds exactly the fp32 bytes it cp.async'd (single fp16, no lo term)
    auto convert = [&](int kc){
        const char* fb = sm + 59392 + (kc & 1)*17408;
        char* bbn = sm + 40960 + (kc & 1)*9216;
#pragma unroll
        for (int m=0;m<2;m++){
#pragma unroll
            for (int p=0;p<2;p++){
                int row = brow + p*16;
                float4 v = *(const float4*)(fb + m*8704 + row*272 + bseg*16);
                uint32_t h0,h1;
                roundf4h(v, h0, h1);
                *(uint2*)(bbn + m*4608 + row*144 + bseg*8) = make_uint2(h0,h1);
            }
        }
    };

    auto compute = [&](int kc){
        uint32_t aB = sb + (kc & 1)*20480 + laneA;
        uint32_t bBase = sb + 40960 + (kc & 1)*9216 + laneBT + (wn*64);
#pragma unroll
        for (int k16=0;k16<2;k16++){
            uint32_t ko = k16*32;
            uint32_t ah[2][4], al[2][4];
            ldsm4(ah[0], aB + ko);
            ldsm4(ah[1], aB + 1280 + ko);
            ldsm4(al[0], aB + 10240 + ko);
            ldsm4(al[1], aB + 11520 + ko);
#pragma unroll
            for (int np=0;np<2;np++){
                uint32_t bo = bBase + k16*2304 + np*32;
                uint32_t bg_[4], bu_[4];
                ldsm4t(bg_, bo);
                ldsm4t(bu_, bo + 4608);
#pragma unroll
                for (int s=0;s<2;s++){
                    int ni = np*2+s;
#pragma unroll
                    for (int mi=0;mi<2;mi++){
                        mma_f16(accG[mi][ni], ah[mi], bg_+2*s);
                        mma_f16(accG[mi][ni], al[mi], bg_+2*s);
                        mma_f16(accU[mi][ni], ah[mi], bu_+2*s);
                        mma_f16(accU[mi][ni], al[mi], bu_+2*s);
                    }
                }
            }
        }
    };

    issue_stage(0);
    cpwait<0>();
    convert(0);
    __syncthreads();

    const int NK = H_DIM/32;  // 32
    for (int kc=0; kc<NK; kc++){
        if (kc+1 < NK) issue_stage(kc+1);
        compute(kc);
        if (kc+1 < NK){
            cpwait<0>();
            convert(kc+1);
        }
        __syncthreads();
    }

    // epilogue: a = silu(g)*u -> g_Ahi/g_Alo (fp16 hi/lo split)
#pragma unroll
    for (int mi=0;mi<2;mi++)
#pragma unroll
        for (int hf=0;hf<2;hf++){
            int row = wm*32 + mi*16 + r0 + hf*8;
            if (row < vr){
                size_t rb = (size_t)(rowbase + row)*I_DIM;
#pragma unroll
                for (int ni=0;ni<4;ni++){
                    int n = n0 + wn*32 + ni*8 + (lane&3)*2;
                    float g0 = accG[mi][ni][hf*2+0], g1 = accG[mi][ni][hf*2+1];
                    float u0 = accU[mi][ni][hf*2+0], u1 = accU[mi][ni][hf*2+1];
                    float a0 = g0/(1.f+expf(-g0))*u0;
                    float a1 = g1/(1.f+expf(-g1))*u1;
                    __half h0=__float2half_rn(a0), h1=__float2half_rn(a1);
                    __half l0=__float2half_rn(a0-__half2float(h0));
                    __half l1=__float2half_rn(a1-__half2float(h1));
                    *(uint32_t*)((char*)g_Ahi + (rb+n)*2) = (uint32_t)hu(h0) | ((uint32_t)hu(h1)<<16);
                    *(uint32_t*)((char*)g_Alo + (rb+n)*2) = (uint32_t)hu(l0) | ((uint32_t)hu(l1)<<16);
                }
            }
        }
}

// ======================== GEMM 2: down + bias + weighted combine (fused round) ==============
// SMEM layout:
//   [0, 40960)        A stages (g_Ahi/g_Alo)
//   [40960, 50176)    B fp16 stages: 40960 + s*4608; [k=32][n=64], stride 144B
//   [50176, 67584)    B fp32 stages: 50176 + s*8704; stride 272B
#define DN_SMEM 67584
__global__ void __launch_bounds__(256,2) k_gemm_down(const float* __restrict__ wd,
                                                     const float* __restrict__ bd,
                                                     float* __restrict__ out){
    const int e = blockIdx.z;
    const int cnt = g_count[e];
    const int m0 = blockIdx.x*128;
    if (m0 >= cnt) return;
    const int n0 = blockIdx.y*64;
    const int rowbase = g_base[e] + m0;
    const int vr = min(128, cnt - m0);

    extern __shared__ char sm[];
    uint32_t sb = s2u(sm);

    const int tid = threadIdx.x;
    const int lane = tid & 31, wid = tid >> 5;
    const int wm = wid & 3, wn = wid >> 2;
    const int r0 = lane >> 2;

    const uint32_t laneA  = (uint32_t)((wm*32 + ((lane>>3)&1)*8 + (lane&7))*80 + (lane>>4)*16);
    const uint32_t laneBT = (uint32_t)((lane&15)*144 + (lane>>4)*16);

    const char* ah = (const char*)g_Ahi + (size_t)rowbase*I_DIM*2;
    const char* al = (const char*)g_Alo + (size_t)rowbase*I_DIM*2;
    const float* wd_p = wd + (size_t)e*I_DIM*H_DIM + n0;
    const size_t strA = (size_t)I_DIM*2;  // 5632

    const int brow = tid >> 4;
    const int bseg = tid & 15;

    float acc[2][4][4] = {};

    auto issue_stage = [&](int kc){
        uint32_t astg = sb + (kc & 1)*20480;
        int kb = kc*64;
#pragma unroll
        for (int c=0;c<4;c++){
            int idx = tid + 256*c;
            int mat = idx >> 9, rem = idx & 511, row = rem >> 2, seg = rem & 3;
            int srow = min(rowbase + row, NSLOT-1) - rowbase;
            const char* s = (mat ? al : ah) + (size_t)srow*strA + kb + seg*16;
            cpa(astg + mat*10240 + row*80 + seg*16, s);
        }
        int kr = kc*32;
        uint32_t fstg = sb + 50176 + (kc & 1)*8704;
#pragma unroll
        for (int p=0;p<2;p++){
            int row = brow + p*16;
            const float* s = wd_p + (size_t)(kr + row)*H_DIM + bseg*4;
            cpa(fstg + row*272 + bseg*16, s);
        }
        cpcommit();
    };

    auto convert = [&](int kc){
        const char* fb = sm + 50176 + (kc & 1)*8704;
        char* bbn = sm + 40960 + (kc & 1)*4608;
#pragma unroll
        for (int p=0;p<2;p++){
            int row = brow + p*16;
            float4 v = *(const float4*)(fb + row*272 + bseg*16);
            uint32_t h0,h1;
            roundf4h(v, h0, h1);
            *(uint2*)(bbn + row*144 + bseg*8) = make_uint2(h0,h1);
        }
    };

    auto compute = [&](int kc){
        uint32_t aB = sb + (kc & 1)*20480 + laneA;
        uint32_t bBase = sb + 40960 + (kc & 1)*4608 + laneBT + (wn*64);
#pragma unroll
        for (int k16=0;k16<2;k16++){
            uint32_t ah_[2][4], al_[2][4];
            uint32_t ko = k16*32;
            ldsm4(ah_[0], aB + ko);
            ldsm4(ah_[1], aB + 1280 + ko);
            ldsm4(al_[0], aB + 10240 + ko);
            ldsm4(al_[1], aB + 11520 + ko);
#pragma unroll
            for (int np=0;np<2;np++){
                uint32_t bw_[4];
                ldsm4t(bw_, bBase + k16*2304 + np*32);
#pragma unroll
                for (int s=0;s<2;s++){
                    int ni = np*2+s;
#pragma unroll
                    for (int mi=0;mi<2;mi++){
                        mma_f16(acc[mi][ni], ah_[mi], bw_+2*s);
                        mma_f16(acc[mi][ni], al_[mi], bw_+2*s);
                    }
                }
            }
        }
    };

    issue_stage(0);
    cpwait<0>();
    convert(0);
    __syncthreads();

    const int NK = I_DIM/32;  // 88
    for (int kc=0; kc<NK; kc++){
        if (kc+1 < NK) issue_stage(kc+1);
        compute(kc);
        if (kc+1 < NK){
            cpwait<0>();
            convert(kc+1);
        }
        __syncthreads();
    }

    // epilogue: out[t] += w * (acc + b_down[e])   (2 commutative adds -> deterministic)
#pragma unroll
    for (int mi=0;mi<2;mi++)
#pragma unroll
        for (int hf=0;hf<2;hf++){
            int row = wm*32 + mi*16 + r0 + hf*8;
            if (row < vr){
                int slot = g_rowtok[rowbase + row];
                float w = g_wgt[slot];
                int t = slot >> 1;
                float* orow = out + (size_t)t*H_DIM;
                const float* brow_ = bd + (size_t)e*H_DIM;
#pragma unroll
                for (int ni=0;ni<4;ni++){
                    int n = n0 + wn*32 + ni*8 + (lane&3)*2;
                    float v0 = (acc[mi][ni][hf*2+0] + brow_[n])   * w;
                    float v1 = (acc[mi][ni][hf*2+1] + brow_[n+1]) * w;
                    atomicAdd(&orow[n],   v0);
                    atomicAdd(&orow[n+1], v1);
                }
            }
        }
}

// ---------------- launch ----------------
extern "C" void kernel_launch(void* const* d_in, const int* in_sizes, int n_in,
                              void* d_out, int out_size){
    const float* x  = (const float*)d_in[0];
    const float* wr = (const float*)d_in[1];
    const float* wg = (const float*)d_in[2];
    const float* wu = (const float*)d_in[3];
    const float* wd = (const float*)d_in[4];
    const float* bd = (const float*)d_in[5];
    float* out = (float*)d_out;

    cudaFuncSetAttribute(k_gemm_gateup, cudaFuncAttributeMaxDynamicSharedMemorySize, GU_SMEM);
    cudaFuncSetAttribute(k_gemm_down,   cudaFuncAttributeMaxDynamicSharedMemorySize, DN_SMEM);

    cudaMemsetAsync(out, 0, (size_t)out_size * sizeof(float));
    k_zero<<<1,32>>>();
    k_router<<<T_TOK/8, 256>>>(x, wr);
    k_prefix<<<1,32>>>();
    k_prep<<<dim3(T_TOK, E_NUM), 256>>>(x);

    k_gemm_gateup<<<dim3(T_TOK/128, I_DIM/64, E_NUM), 256, GU_SMEM>>>(wg, wu);
    k_gemm_down  <<<dim3(T_TOK/128, H_DIM/64, E_NUM), 256, DN_SMEM>>>(wd, bd, out);
}

// round 9
// speedup vs baseline: 5.8024x; 1.3002x over previous
#include <cuda_runtime.h>
#include <cuda_fp16.h>
#include <math.h>
#include <stdint.h>

#define T_TOK 2048
#define H_DIM 1024
#define E_NUM 8
#define I_DIM 2816
#define NSLOT (2*T_TOK)

// ---------------- device scratch ----------------
__device__ int   g_count[E_NUM];
__device__ int   g_base[E_NUM];
__device__ int   g_tok[E_NUM*T_TOK];
__device__ float g_wgt[NSLOT];
__device__ int   g_rowtok[NSLOT];
__device__ __half g_X[(size_t)NSLOT*H_DIM];
__device__ __half g_A[(size_t)NSLOT*I_DIM];

// ---------------- helpers ----------------
__device__ __forceinline__ uint32_t s2u(const void* p){
    uint32_t a;
    asm("{ .reg .u64 t; cvta.to.shared.u64 t, %1; cvt.u32.u64 %0, t; }" : "=r"(a) : "l"(p));
    return a;
}
__device__ __forceinline__ void cpa(uint32_t dst, const void* src){
    asm volatile("cp.async.cg.shared.global [%0], [%1], 16;" :: "r"(dst), "l"(src));
}
__device__ __forceinline__ void cpcommit(){ asm volatile("cp.async.commit_group;" ::: "memory"); }
template<int N> __device__ __forceinline__ void cpwait(){ asm volatile("cp.async.wait_group %0;" :: "n"(N) : "memory"); }

__device__ __forceinline__ void ldsm4(uint32_t* r, uint32_t a){
    asm volatile("ldmatrix.sync.aligned.m8n8.x4.shared.b16 {%0,%1,%2,%3}, [%4];"
        : "=r"(r[0]), "=r"(r[1]), "=r"(r[2]), "=r"(r[3]) : "r"(a));
}
__device__ __forceinline__ void ldsm4t(uint32_t* r, uint32_t a){
    asm volatile("ldmatrix.sync.aligned.m8n8.x4.trans.shared.b16 {%0,%1,%2,%3}, [%4];"
        : "=r"(r[0]), "=r"(r[1]), "=r"(r[2]), "=r"(r[3]) : "r"(a));
}
__device__ __forceinline__ void mma_f16(float* d, const uint32_t* a, const uint32_t* b){
    asm volatile(
        "mma.sync.aligned.m16n8k16.row.col.f32.f16.f16.f32 "
        "{%0,%1,%2,%3}, {%4,%5,%6,%7}, {%8,%9}, {%0,%1,%2,%3};"
        : "+f"(d[0]), "+f"(d[1]), "+f"(d[2]), "+f"(d[3])
        : "r"(a[0]), "r"(a[1]), "r"(a[2]), "r"(a[3]), "r"(b[0]), "r"(b[1]));
}
__device__ __forceinline__ unsigned short hu(__half b){
    return *reinterpret_cast<unsigned short*>(&b);
}
__device__ __forceinline__ uint32_t h2u(__half2 v){
    return *reinterpret_cast<uint32_t*>(&v);
}
// round a float4 to packed fp16 pairs
__device__ __forceinline__ void roundf4h(float4 v, uint32_t& h0, uint32_t& h1){
    h0 = h2u(__floats2half2_rn(v.x, v.y));
    h1 = h2u(__floats2half2_rn(v.z, v.w));
}

// ---------------- small kernels ----------------
__global__ void k_zero(){ if (threadIdx.x < E_NUM) g_count[threadIdx.x] = 0; }

__global__ void k_router(const float* __restrict__ x, const float* __restrict__ wr){
    int t = blockIdx.x*8 + (threadIdx.x>>5);
    int lane = threadIdx.x & 31;
    if (t >= T_TOK) return;
    float acc[E_NUM];
#pragma unroll
    for (int e=0;e<E_NUM;e++) acc[e]=0.f;
    const float* xr = x + (size_t)t*H_DIM;
    for (int h=lane; h<H_DIM; h+=32){
        float xv = xr[h];
        const float* wrow = wr + (size_t)h*E_NUM;
#pragma unroll
        for (int e=0;e<E_NUM;e++) acc[e] += xv*wrow[e];
    }
#pragma unroll
    for (int off=16; off>0; off>>=1)
#pragma unroll
        for (int e=0;e<E_NUM;e++) acc[e] += __shfl_down_sync(0xFFFFFFFFu, acc[e], off);
    if (lane==0){
        int i0=0; float v0=acc[0];
#pragma unroll
        for (int e=1;e<E_NUM;e++) if (acc[e]>v0){ v0=acc[e]; i0=e; }
        int i1=-1; float v1=-INFINITY;
#pragma unroll
        for (int e=0;e<E_NUM;e++){ if (e==i0) continue; if (acc[e]>v1){ v1=acc[e]; i1=e; } }
        float w0 = 1.f/(1.f+expf(v1-v0));
        float w1 = 1.f - w0;
        int p0 = atomicAdd(&g_count[i0],1); g_tok[i0*T_TOK+p0] = 2*t;
        int p1 = atomicAdd(&g_count[i1],1); g_tok[i1*T_TOK+p1] = 2*t+1;
        g_wgt[2*t]=w0; g_wgt[2*t+1]=w1;
    }
}

__global__ void k_prefix(){
    if (threadIdx.x==0){
        int s=0;
#pragma unroll
        for (int e=0;e<E_NUM;e++){ g_base[e]=s; s+=g_count[e]; }
    }
}

__global__ void __launch_bounds__(256) k_prep(const float* __restrict__ x){
    int e = blockIdx.y, p = blockIdx.x;
    if (p >= g_count[e]) return;
    int r = g_base[e] + p;
    int slot = g_tok[e*T_TOK + p];
    if (threadIdx.x==0) g_rowtok[r] = slot;
    int t = slot >> 1;
    float4 v = ((const float4*)(x + (size_t)t*H_DIM))[threadIdx.x];
    uint32_t h0,h1;
    roundf4h(v, h0, h1);
    *(uint2*)(g_X + (size_t)r*H_DIM + threadIdx.x*4) = make_uint2(h0,h1);
}

// ======================== GEMM 1: gate+up (pure fp16, fused weight round) ========================
// CTA 128(M) x 64(N), K chunks of 32, 8 warps (4M x 2N), warp tile 32x32.
// SMEM layout:
//   [0, 20480)        A stages: s*10240; 128 rows x 80B
//   [20480, 38912)    B fp16 stages: 20480 + s*9216; G+0, U+4608; [k=32][n=64], stride 144B
//   [38912, 73728)    B fp32 stages: 38912 + s*17408; gate+0, up+8704; stride 272B
#define GU_SMEM 73728
__global__ void __launch_bounds__(256,2) k_gemm_gateup(const float* __restrict__ wg,
                                                       const float* __restrict__ wu){
    const int e = blockIdx.z;
    const int cnt = g_count[e];
    const int m0 = blockIdx.x*128;
    if (m0 >= cnt) return;
    const int n0 = blockIdx.y*64;
    const int rowbase = g_base[e] + m0;
    const int vr = min(128, cnt - m0);

    extern __shared__ char sm[];
    uint32_t sb = s2u(sm);

    const int tid = threadIdx.x;
    const int lane = tid & 31, wid = tid >> 5;
    const int wm = wid & 3, wn = wid >> 2;
    const int r0 = lane >> 2;

    const uint32_t laneA  = (uint32_t)((wm*32 + ((lane>>3)&1)*8 + (lane&7))*80 + (lane>>4)*16);
    const uint32_t laneBT = (uint32_t)((lane&15)*144 + (lane>>4)*16);

    const char* xp = (const char*)g_X + (size_t)rowbase*H_DIM*2;
    const float* wg_p = wg + (size_t)e*H_DIM*I_DIM + n0;
    const float* wu_p = wu + (size_t)e*H_DIM*I_DIM + n0;

    const int brow = tid >> 4;         // 0..15
    const int bseg = tid & 15;         // 0..15 (16B columns)

    float accG[2][4][4] = {};
    float accU[2][4][4] = {};

    auto issue_stage = [&](int kc){
        uint32_t astg = sb + (kc & 1)*10240;
        int kb = kc*64;
#pragma unroll
        for (int c=0;c<2;c++){   // A fp16: 512 x 16B
            int idx = tid + 256*c;
            int row = idx >> 2, seg = idx & 3;
            int srow = min(rowbase + row, NSLOT-1) - rowbase;
            const char* s = xp + (size_t)srow*2048 + kb + seg*16;
            cpa(astg + row*80 + seg*16, s);
        }
        int kr = kc*32;
        uint32_t fstg = sb + 38912 + (kc & 1)*17408;
#pragma unroll
        for (int c=0;c<4;c++){   // B fp32 (own-data mapping)
            int m = c >> 1, p = c & 1;
            int row = brow + p*16;
            const float* s = (m ? wu_p : wg_p) + (size_t)(kr + row)*I_DIM + bseg*4;
            cpa(fstg + m*8704 + row*272 + bseg*16, s);
        }
        cpcommit();
    };

    // each thread rounds exactly the fp32 bytes it cp.async'd (visible after cpwait)
    auto convert = [&](int kc){
        const char* fb = sm + 38912 + (kc & 1)*17408;
        char* bbn = sm + 20480 + (kc & 1)*9216;
#pragma unroll
        for (int m=0;m<2;m++){
#pragma unroll
            for (int p=0;p<2;p++){
                int row = brow + p*16;
                float4 v = *(const float4*)(fb + m*8704 + row*272 + bseg*16);
                uint32_t h0,h1;
                roundf4h(v, h0, h1);
                *(uint2*)(bbn + m*4608 + row*144 + bseg*8) = make_uint2(h0,h1);
            }
        }
    };

    auto compute = [&](int kc){
        uint32_t aB = sb + (kc & 1)*10240 + laneA;
        uint32_t bBase = sb + 20480 + (kc & 1)*9216 + laneBT + (wn*64);
#pragma unroll
        for (int k16=0;k16<2;k16++){
            uint32_t ko = k16*32;
            uint32_t ah[2][4];
            ldsm4(ah[0], aB + ko);
            ldsm4(ah[1], aB + 1280 + ko);
#pragma unroll
            for (int np=0;np<2;np++){
                uint32_t bo = bBase + k16*2304 + np*32;
                uint32_t bg_[4], bu_[4];
                ldsm4t(bg_, bo);
                ldsm4t(bu_, bo + 4608);
#pragma unroll
                for (int s=0;s<2;s++){
                    int ni = np*2+s;
#pragma unroll
                    for (int mi=0;mi<2;mi++){
                        mma_f16(accG[mi][ni], ah[mi], bg_+2*s);
                        mma_f16(accU[mi][ni], ah[mi], bu_+2*s);
                    }
                }
            }
        }
    };

    issue_stage(0);
    cpwait<0>();
    convert(0);
    __syncthreads();

    const int NK = H_DIM/32;  // 32
    for (int kc=0; kc<NK; kc++){
        if (kc+1 < NK) issue_stage(kc+1);
        compute(kc);
        if (kc+1 < NK){
            cpwait<0>();
            convert(kc+1);
        }
        __syncthreads();
    }

    // epilogue: a = silu(g)*u -> g_A (fp16)
#pragma unroll
    for (int mi=0;mi<2;mi++)
#pragma unroll
        for (int hf=0;hf<2;hf++){
            int row = wm*32 + mi*16 + r0 + hf*8;
            if (row < vr){
                size_t rb = (size_t)(rowbase + row)*I_DIM;
#pragma unroll
                for (int ni=0;ni<4;ni++){
                    int n = n0 + wn*32 + ni*8 + (lane&3)*2;
                    float g0 = accG[mi][ni][hf*2+0], g1 = accG[mi][ni][hf*2+1];
                    float u0 = accU[mi][ni][hf*2+0], u1 = accU[mi][ni][hf*2+1];
                    float a0 = g0/(1.f+expf(-g0))*u0;
                    float a1 = g1/(1.f+expf(-g1))*u1;
                    *(uint32_t*)((char*)g_A + (rb+n)*2) = h2u(__floats2half2_rn(a0, a1));
                }
            }
        }
}

// ======================== GEMM 2: down + bias + weighted combine (pure fp16) ==============
// SMEM layout:
//   [0, 20480)        A stages: s*10240
//   [20480, 29696)    B fp16 stages: 20480 + s*4608; [k=32][n=64], stride 144B
//   [29696, 47104)    B fp32 stages: 29696 + s*8704; stride 272B
#define DN_SMEM 47104
__global__ void __launch_bounds__(256,2) k_gemm_down(const float* __restrict__ wd,
                                                     const float* __restrict__ bd,
                                                     float* __restrict__ out){
    const int e = blockIdx.z;
    const int cnt = g_count[e];
    const int m0 = blockIdx.x*128;
    if (m0 >= cnt) return;
    const int n0 = blockIdx.y*64;
    const int rowbase = g_base[e] + m0;
    const int vr = min(128, cnt - m0);

    extern __shared__ char sm[];
    uint32_t sb = s2u(sm);

    const int tid = threadIdx.x;
    const int lane = tid & 31, wid = tid >> 5;
    const int wm = wid & 3, wn = wid >> 2;
    const int r0 = lane >> 2;

    const uint32_t laneA  = (uint32_t)((wm*32 + ((lane>>3)&1)*8 + (lane&7))*80 + (lane>>4)*16);
    const uint32_t laneBT = (uint32_t)((lane&15)*144 + (lane>>4)*16);

    const char* ap = (const char*)g_A + (size_t)rowbase*I_DIM*2;
    const float* wd_p = wd + (size_t)e*I_DIM*H_DIM + n0;
    const size_t strA = (size_t)I_DIM*2;  // 5632

    const int brow = tid >> 4;
    const int bseg = tid & 15;

    float acc[2][4][4] = {};

    auto issue_stage = [&](int kc){
        uint32_t astg = sb + (kc & 1)*10240;
        int kb = kc*64;
#pragma unroll
        for (int c=0;c<2;c++){
            int idx = tid + 256*c;
            int row = idx >> 2, seg = idx & 3;
            int srow = min(rowbase + row, NSLOT-1) - rowbase;
            const char* s = ap + (size_t)srow*strA + kb + seg*16;
            cpa(astg + row*80 + seg*16, s);
        }
        int kr = kc*32;
        uint32_t fstg = sb + 29696 + (kc & 1)*8704;
#pragma unroll
        for (int p=0;p<2;p++){
            int row = brow + p*16;
            const float* s = wd_p + (size_t)(kr + row)*H_DIM + bseg*4;
            cpa(fstg + row*272 + bseg*16, s);
        }
        cpcommit();
    };

    auto convert = [&](int kc){
        const char* fb = sm + 29696 + (kc & 1)*8704;
        char* bbn = sm + 20480 + (kc & 1)*4608;
#pragma unroll
        for (int p=0;p<2;p++){
            int row = brow + p*16;
            float4 v = *(const float4*)(fb + row*272 + bseg*16);
            uint32_t h0,h1;
            roundf4h(v, h0, h1);
            *(uint2*)(bbn + row*144 + bseg*8) = make_uint2(h0,h1);
        }
    };

    auto compute = [&](int kc){
        uint32_t aB = sb + (kc & 1)*10240 + laneA;
        uint32_t bBase = sb + 20480 + (kc & 1)*4608 + laneBT + (wn*64);
#pragma unroll
        for (int k16=0;k16<2;k16++){
            uint32_t ah_[2][4];
            uint32_t ko = k16*32;
            ldsm4(ah_[0], aB + ko);
            ldsm4(ah_[1], aB + 1280 + ko);
#pragma unroll
            for (int np=0;np<2;np++){
                uint32_t bw_[4];
                ldsm4t(bw_, bBase + k16*2304 + np*32);
#pragma unroll
                for (int s=0;s<2;s++){
                    int ni = np*2+s;
#pragma unroll
                    for (int mi=0;mi<2;mi++){
                        mma_f16(acc[mi][ni], ah_[mi], bw_+2*s);
                    }
                }
            }
        }
    };

    issue_stage(0);
    cpwait<0>();
    convert(0);
    __syncthreads();

    const int NK = I_DIM/32;  // 88
    for (int kc=0; kc<NK; kc++){
        if (kc+1 < NK) issue_stage(kc+1);
        compute(kc);
        if (kc+1 < NK){
            cpwait<0>();
            convert(kc+1);
        }
        __syncthreads();
    }

    // epilogue: out[t] += w * (acc + b_down[e])   (2 commutative adds -> deterministic)
#pragma unroll
    for (int mi=0;mi<2;mi++)
#pragma unroll
        for (int hf=0;hf<2;hf++){
            int row = wm*32 + mi*16 + r0 + hf*8;
            if (row < vr){
                int slot = g_rowtok[rowbase + row];
                float w = g_wgt[slot];
                int t = slot >> 1;
                float* orow = out + (size_t)t*H_DIM;
                const float* brow_ = bd + (size_t)e*H_DIM;
#pragma unroll
                for (int ni=0;ni<4;ni++){
                    int n = n0 + wn*32 + ni*8 + (lane&3)*2;
                    float v0 = (acc[mi][ni][hf*2+0] + brow_[n])   * w;
                    float v1 = (acc[mi][ni][hf*2+1] + brow_[n+1]) * w;
                    atomicAdd(&orow[n],   v0);
                    atomicAdd(&orow[n+1], v1);
                }
            }
        }
}

// ---------------- launch ----------------
extern "C" void kernel_launch(void* const* d_in, const int* in_sizes, int n_in,
                              void* d_out, int out_size){
    const float* x  = (const float*)d_in[0];
    const float* wr = (const float*)d_in[1];
    const float* wg = (const float*)d_in[2];
    const float* wu = (const float*)d_in[3];
    const float* wd = (const float*)d_in[4];
    const float* bd = (const float*)d_in[5];
    float* out = (float*)d_out;

    cudaFuncSetAttribute(k_gemm_gateup, cudaFuncAttributeMaxDynamicSharedMemorySize, GU_SMEM);
    cudaFuncSetAttribute(k_gemm_down,   cudaFuncAttributeMaxDynamicSharedMemorySize, DN_SMEM);

    cudaMemsetAsync(out, 0, (size_t)out_size * sizeof(float));
    k_zero<<<1,32>>>();
    k_router<<<T_TOK/8, 256>>>(x, wr);
    k_prefix<<<1,32>>>();
    k_prep<<<dim3(T_TOK, E_NUM), 256>>>(x);

    k_gemm_gateup<<<dim3(T_TOK/128, I_DIM/64, E_NUM), 256, GU_SMEM>>>(wg, wu);
    k_gemm_down  <<<dim3(T_TOK/128, H_DIM/64, E_NUM), 256, DN_SMEM>>>(wd, bd, out);
}